// round 3
// baseline (speedup 1.0000x reference)
#include <cuda_runtime.h>
#include <math.h>

#define DD 256
#define N_MAX 10000
#define E_MAX 320000
#define ET_MAX (E_MAX + N_MAX)

// ---------------- scratch (device globals; no allocation allowed) ----------
__device__ float g_xw1[N_MAX * DD];   // x @ W1
__device__ float g_x1 [N_MAX * DD];   // relu(GCN out)  (layer-2 input)
__device__ float g_xw2[N_MAX * DD];   // x1 @ W2
__device__ float g_as[N_MAX];         // xw2 . att_src  (per node)
__device__ float g_ad[N_MAX];         // xw2 . att_dst
__device__ float g_dinv[N_MAX];       // rsqrt(deg)
__device__ int   g_cnt[N_MAX];        // in-degree incl self loop
__device__ int   g_rowptr[N_MAX + 1];
__device__ int   g_wp[N_MAX];         // write cursors
__device__ int   g_srcs[ET_MAX];      // CSR(src) sorted by dst

// ---------------- CSR build -------------------------------------------------
__global__ void k_init_cnt(int n) {
    int i = blockIdx.x * blockDim.x + threadIdx.x;
    if (i < n) g_cnt[i] = 1;   // self loop
}

__global__ void k_count(const int* __restrict__ dst, int E) {
    int e = blockIdx.x * blockDim.x + threadIdx.x;
    if (e < E) atomicAdd(&g_cnt[dst[e]], 1);
}

// single-block exclusive scan over n<=10240 counters; also dinv
__global__ void k_scan(int n) {
    __shared__ int sums[1024];
    int t = threadIdx.x;
    int CH = (n + 1023) / 1024;
    int base = t * CH;
    int local = 0;
    for (int i = 0; i < CH; i++) {
        int idx = base + i;
        if (idx < n) {
            int c = g_cnt[idx];
            local += c;
            g_dinv[idx] = rsqrtf((float)c);
        }
    }
    sums[t] = local;
    __syncthreads();
    for (int off = 1; off < 1024; off <<= 1) {
        int v = 0;
        if (t >= off) v = sums[t - off];
        __syncthreads();
        if (t >= off) sums[t] += v;
        __syncthreads();
    }
    int run = (t == 0) ? 0 : sums[t - 1];
    for (int i = 0; i < CH; i++) {
        int idx = base + i;
        if (idx < n) {
            g_rowptr[idx] = run;
            run += g_cnt[idx];
        }
    }
    if (t == 0) g_rowptr[n] = sums[1023];
}

__global__ void k_self(int n) {
    int i = blockIdx.x * blockDim.x + threadIdx.x;
    if (i < n) {
        int p = g_rowptr[i];
        g_srcs[p] = i;       // self loop first
        g_wp[i] = p + 1;
    }
}

__global__ void k_scatter(const int* __restrict__ src, const int* __restrict__ dst, int E) {
    int e = blockIdx.x * blockDim.x + threadIdx.x;
    if (e < E) {
        int d = dst[e];
        int pos = atomicAdd(&g_wp[d], 1);
        g_srcs[pos] = src[e];
    }
}

// ---------------- SGEMM: C[M,256] = A[M,256] @ B[256,256] ------------------
// classic 128x128x8 register-blocked fp32 GEMM, 256 threads, TM=TN=8
__global__ void sgemm_k(const float* __restrict__ Ain, const float* __restrict__ B,
                        int M, int which) {
    const float* __restrict__ A = which ? g_x1 : Ain;
    float* __restrict__ C = which ? g_xw2 : g_xw1;
    const int K = DD, Nn = DD;
    __shared__ float As[8][128];
    __shared__ float Bs[8][128];
    int tid = threadIdx.x;
    int blockRow = blockIdx.x * 128;
    int blockCol = blockIdx.y * 128;
    int aRow = tid >> 1;
    int aCol = (tid & 1) * 4;
    int bRow = tid >> 5;
    int bCol = (tid & 31) * 4;
    int tr = (tid >> 4) * 8;
    int tc = (tid & 15) * 8;
    float acc[8][8];
#pragma unroll
    for (int i = 0; i < 8; i++)
#pragma unroll
        for (int j = 0; j < 8; j++) acc[i][j] = 0.0f;

    for (int k0 = 0; k0 < K; k0 += 8) {
        float4 a4 = make_float4(0.f, 0.f, 0.f, 0.f);
        int gr = blockRow + aRow;
        if (gr < M) a4 = *(const float4*)(A + (size_t)gr * K + k0 + aCol);
        As[aCol + 0][aRow] = a4.x;
        As[aCol + 1][aRow] = a4.y;
        As[aCol + 2][aRow] = a4.z;
        As[aCol + 3][aRow] = a4.w;
        float4 b4 = *(const float4*)(B + (size_t)(k0 + bRow) * Nn + blockCol + bCol);
        *(float4*)&Bs[bRow][bCol] = b4;
        __syncthreads();
#pragma unroll
        for (int kk = 0; kk < 8; kk++) {
            float4 ra0 = *(const float4*)&As[kk][tr];
            float4 ra1 = *(const float4*)&As[kk][tr + 4];
            float4 rb0 = *(const float4*)&Bs[kk][tc];
            float4 rb1 = *(const float4*)&Bs[kk][tc + 4];
            float ra[8] = {ra0.x, ra0.y, ra0.z, ra0.w, ra1.x, ra1.y, ra1.z, ra1.w};
            float rb[8] = {rb0.x, rb0.y, rb0.z, rb0.w, rb1.x, rb1.y, rb1.z, rb1.w};
#pragma unroll
            for (int i = 0; i < 8; i++)
#pragma unroll
                for (int j = 0; j < 8; j++) acc[i][j] += ra[i] * rb[j];
        }
        __syncthreads();
    }
#pragma unroll
    for (int i = 0; i < 8; i++) {
        int gr = blockRow + tr + i;
        if (gr < M) {
            float4 v0 = make_float4(acc[i][0], acc[i][1], acc[i][2], acc[i][3]);
            float4 v1 = make_float4(acc[i][4], acc[i][5], acc[i][6], acc[i][7]);
            *(float4*)(C + (size_t)gr * Nn + blockCol + tc) = v0;
            *(float4*)(C + (size_t)gr * Nn + blockCol + tc + 4) = v1;
        }
    }
}

// ---------------- GCN aggregation: warp per node ---------------------------
__global__ void gcn_agg(const float* __restrict__ b1, int n) {
    int warp = (blockIdx.x * blockDim.x + threadIdx.x) >> 5;
    if (warp >= n) return;
    int lane = threadIdx.x & 31;
    float di = g_dinv[warp];
    int s = g_rowptr[warp], e = g_rowptr[warp + 1];
    float4 acc0 = make_float4(0.f, 0.f, 0.f, 0.f);
    float4 acc1 = make_float4(0.f, 0.f, 0.f, 0.f);
    for (int i = s; i < e; i++) {
        int src = g_srcs[i];                     // broadcast
        float w = di * g_dinv[src];
        const float4* p = (const float4*)(g_xw1 + (size_t)src * DD);
        float4 v0 = p[lane];
        float4 v1 = p[lane + 32];
        acc0.x += w * v0.x; acc0.y += w * v0.y; acc0.z += w * v0.z; acc0.w += w * v0.w;
        acc1.x += w * v1.x; acc1.y += w * v1.y; acc1.z += w * v1.z; acc1.w += w * v1.w;
    }
    const float4* bb = (const float4*)b1;
    float4 b0 = bb[lane], b1v = bb[lane + 32];
    float4 o0 = make_float4(fmaxf(acc0.x + b0.x, 0.f), fmaxf(acc0.y + b0.y, 0.f),
                            fmaxf(acc0.z + b0.z, 0.f), fmaxf(acc0.w + b0.w, 0.f));
    float4 o1 = make_float4(fmaxf(acc1.x + b1v.x, 0.f), fmaxf(acc1.y + b1v.y, 0.f),
                            fmaxf(acc1.z + b1v.z, 0.f), fmaxf(acc1.w + b1v.w, 0.f));
    float4* out = (float4*)(g_x1 + (size_t)warp * DD);
    out[lane] = o0;
    out[lane + 32] = o1;
}

// ---------------- attention dot products: warp per node --------------------
__global__ void att_dots(const float* __restrict__ att_src,
                         const float* __restrict__ att_dst, int n) {
    int warp = (blockIdx.x * blockDim.x + threadIdx.x) >> 5;
    if (warp >= n) return;
    int lane = threadIdx.x & 31;
    const float4* x = (const float4*)(g_xw2 + (size_t)warp * DD);
    const float4* a = (const float4*)att_src;
    const float4* b = (const float4*)att_dst;
    float ss = 0.f, dd = 0.f;
#pragma unroll
    for (int j = 0; j < 2; j++) {
        float4 v = x[lane + 32 * j];
        float4 va = a[lane + 32 * j];
        float4 vb = b[lane + 32 * j];
        ss += v.x * va.x + v.y * va.y + v.z * va.z + v.w * va.w;
        dd += v.x * vb.x + v.y * vb.y + v.z * vb.z + v.w * vb.w;
    }
#pragma unroll
    for (int off = 16; off > 0; off >>= 1) {
        ss += __shfl_xor_sync(0xffffffffu, ss, off);
        dd += __shfl_xor_sync(0xffffffffu, dd, off);
    }
    if (lane == 0) {
        g_as[warp] = ss;
        g_ad[warp] = dd;
    }
}

// ---------------- GAT aggregation: warp per node ---------------------------
__global__ void gat_agg(const float* __restrict__ b2, float* __restrict__ out, int n) {
    int warp = (blockIdx.x * blockDim.x + threadIdx.x) >> 5;
    if (warp >= n) return;
    int lane = threadIdx.x & 31;
    int s = g_rowptr[warp], e = g_rowptr[warp + 1];
    float ad_n = g_ad[warp];

    // pass 1: per-lane online softmax stats over strided edges
    float m = -INFINITY, sum = 0.f;
    for (int i = s + lane; i < e; i += 32) {
        int src = g_srcs[i];
        float ev = g_as[src] + ad_n;
        ev = (ev >= 0.f) ? ev : 0.2f * ev;
        if (ev > m) {
            sum = sum * expf(m - ev) + 1.0f;  // sum==0 first time; exp(-inf)=0
            m = ev;
        } else {
            sum += expf(ev - m);
        }
    }
    // warp reduce (m, sum) with rescale; guard -inf/-inf
#pragma unroll
    for (int off = 16; off > 0; off >>= 1) {
        float mo = __shfl_xor_sync(0xffffffffu, m, off);
        float so = __shfl_xor_sync(0xffffffffu, sum, off);
        float mn = fmaxf(m, mo);
        float sa = (m == mn) ? sum : sum * expf(m - mn);
        float sb = (mo == mn) ? so : so * expf(mo - mn);
        sum = sa + sb;
        m = mn;
    }
    float inv = 1.0f / (sum + 1e-16f);

    // pass 2: weighted accumulate (all lanes recompute the scalar edge weight)
    float4 acc0 = make_float4(0.f, 0.f, 0.f, 0.f);
    float4 acc1 = make_float4(0.f, 0.f, 0.f, 0.f);
    for (int i = s; i < e; i++) {
        int src = g_srcs[i];                     // broadcast
        float ev = g_as[src] + ad_n;
        ev = (ev >= 0.f) ? ev : 0.2f * ev;
        float w = expf(ev - m) * inv;
        const float4* p = (const float4*)(g_xw2 + (size_t)src * DD);
        float4 v0 = p[lane];
        float4 v1 = p[lane + 32];
        acc0.x += w * v0.x; acc0.y += w * v0.y; acc0.z += w * v0.z; acc0.w += w * v0.w;
        acc1.x += w * v1.x; acc1.y += w * v1.y; acc1.z += w * v1.z; acc1.w += w * v1.w;
    }
    const float4* bb = (const float4*)b2;
    float4 b0 = bb[lane], b1v = bb[lane + 32];
    float4 o0 = make_float4(fmaxf(acc0.x + b0.x, 0.f), fmaxf(acc0.y + b0.y, 0.f),
                            fmaxf(acc0.z + b0.z, 0.f), fmaxf(acc0.w + b0.w, 0.f));
    float4 o1 = make_float4(fmaxf(acc1.x + b1v.x, 0.f), fmaxf(acc1.y + b1v.y, 0.f),
                            fmaxf(acc1.z + b1v.z, 0.f), fmaxf(acc1.w + b1v.w, 0.f));
    float4* op = (float4*)(out + (size_t)warp * DD);
    op[lane] = o0;
    op[lane + 32] = o1;
}

// ---------------- launch ----------------------------------------------------
extern "C" void kernel_launch(void* const* d_in, const int* in_sizes, int n_in,
                              void* d_out, int out_size) {
    const float* x       = (const float*)d_in[0];   // [N,256]
    const int*   ei      = (const int*)  d_in[1];   // [2,E]
    const float* W1      = (const float*)d_in[2];   // [256,256]
    const float* b1      = (const float*)d_in[3];   // [256]
    const float* W2      = (const float*)d_in[4];   // [256,256]
    const float* att_src = (const float*)d_in[5];   // [256]
    const float* att_dst = (const float*)d_in[6];   // [256]
    const float* b2      = (const float*)d_in[7];   // [256]
    float* out = (float*)d_out;

    int n = in_sizes[0] / DD;
    int E = in_sizes[1] / 2;
    if (n > N_MAX) n = N_MAX;
    if (E > E_MAX) E = E_MAX;
    const int* src = ei;
    const int* dst = ei + E;

    dim3 ggrid((n + 127) / 128, 2);

    k_init_cnt<<<(n + 255) / 256, 256>>>(n);
    sgemm_k<<<ggrid, 256>>>(x, W1, n, 0);                 // g_xw1 = x @ W1
    k_count<<<(E + 255) / 256, 256>>>(dst, E);
    k_scan<<<1, 1024>>>(n);
    k_self<<<(n + 255) / 256, 256>>>(n);
    k_scatter<<<(E + 255) / 256, 256>>>(src, dst, E);
    gcn_agg<<<(n + 7) / 8, 256>>>(b1, n);                 // g_x1 = relu(GCN)
    sgemm_k<<<ggrid, 256>>>(x, W2, n, 1);                 // g_xw2 = g_x1 @ W2
    att_dots<<<(n + 7) / 8, 256>>>(att_src, att_dst, n);
    gat_agg<<<(n + 7) / 8, 256>>>(b2, out, n);            // out = relu(GAT)
}

// round 4
// speedup vs baseline: 1.0338x; 1.0338x over previous
#include <cuda_runtime.h>
#include <math.h>
#include <stdint.h>

#define DD 256
#define N_MAX 10000
#define E_MAX 320000
#define ET_MAX (E_MAX + N_MAX)
#define NB_MAX 64

// ---------------- scratch (device globals; no allocation allowed) ----------
__device__ float g_xw1[N_MAX * DD];   // x @ W1
__device__ float g_x1 [N_MAX * DD];   // relu(GCN out)  (layer-2 input)
__device__ float g_xw2[N_MAX * DD];   // x1 @ W2
__device__ float g_as[N_MAX];         // xw2 . att_src  (per node)
__device__ float g_ad[N_MAX];         // xw2 . att_dst
__device__ float g_dinv[N_MAX];       // rsqrt(deg)
__device__ int   g_cnt[N_MAX];        // in-degree incl self loop
__device__ int   g_rowptr[N_MAX + 1];
__device__ int   g_wp[N_MAX];         // write cursors
__device__ int   g_srcs[ET_MAX];      // CSR(src) sorted by dst
__device__ int   g_bsum[NB_MAX];
__device__ int   g_boff[NB_MAX];

// ---------------- CSR build -------------------------------------------------
__global__ void k_init_cnt(int n) {
    int i = blockIdx.x * blockDim.x + threadIdx.x;
    if (i < n) g_cnt[i] = 1;   // self loop
}

__global__ void k_count(const int* __restrict__ dst, int E) {
    int e = blockIdx.x * blockDim.x + threadIdx.x;
    if (e < E) atomicAdd(&g_cnt[dst[e]], 1);
}

// parallel scan stage 1: per-256-block local exclusive scan + block sums + dinv
__global__ void k_scan1(int n) {
    int i = blockIdx.x * 256 + threadIdx.x;
    int c = (i < n) ? g_cnt[i] : 0;
    if (i < n) g_dinv[i] = rsqrtf((float)c);
    int lane = threadIdx.x & 31, w = threadIdx.x >> 5;
    int v = c;
#pragma unroll
    for (int o = 1; o < 32; o <<= 1) {
        int t = __shfl_up_sync(0xffffffffu, v, o);
        if (lane >= o) v += t;
    }
    __shared__ int ws[8];
    if (lane == 31) ws[w] = v;
    __syncthreads();
    if (w == 0 && lane < 8) {
        int s = ws[lane];
#pragma unroll
        for (int o = 1; o < 8; o <<= 1) {
            int t = __shfl_up_sync(0xffu, s, o);
            if (lane >= o) s += t;
        }
        ws[lane] = s;
    }
    __syncthreads();
    int excl = v - c + (w ? ws[w - 1] : 0);
    if (i < n) g_rowptr[i] = excl;           // local exclusive prefix
    if (threadIdx.x == 0) g_bsum[blockIdx.x] = ws[7];
}

// stage 2: one warp scans <=64 block sums into exclusive offsets + total
__global__ void k_scan2(int nb, int n) {
    int lane = threadIdx.x;
    int v0 = (lane < nb) ? g_bsum[lane] : 0;
    int v1 = (lane + 32 < nb) ? g_bsum[lane + 32] : 0;
    int s0 = v0, s1 = v1;
#pragma unroll
    for (int o = 1; o < 32; o <<= 1) {
        int t = __shfl_up_sync(0xffffffffu, s0, o);
        if (lane >= o) s0 += t;
        int t1 = __shfl_up_sync(0xffffffffu, s1, o);
        if (lane >= o) s1 += t1;
    }
    int tot0 = __shfl_sync(0xffffffffu, s0, 31);
    s1 += tot0;
    g_boff[lane] = s0 - v0;
    g_boff[lane + 32] = s1 - v1;
    if (lane == 31) g_rowptr[n] = s1;
}

// stage 3: apply offsets + plant self-loop + init write cursors
__global__ void k_scan3_self(int n) {
    int i = blockIdx.x * blockDim.x + threadIdx.x;
    if (i < n) {
        int p = g_rowptr[i] + g_boff[i >> 8];
        g_rowptr[i] = p;
        g_srcs[p] = i;       // self loop first
        g_wp[i] = p + 1;
    }
}

__global__ void k_scatter(const int* __restrict__ src, const int* __restrict__ dst, int E) {
    int e = blockIdx.x * blockDim.x + threadIdx.x;
    if (e < E) {
        int d = dst[e];
        int pos = atomicAdd(&g_wp[d], 1);
        g_srcs[pos] = src[e];
    }
}

// ---------------- tensor-core 3xTF32 GEMM: C[M,256]=A[M,256]@B[256,256] ----
// block 128x128, 8 warps (2x4), warp tile 64x32, mma m16n8k8 tf32, fp32 accum.
// 3xTF32: A=Ah+Al, B=Bh+Bl (tf32 splits); D += Al*Bh + Ah*Bl + Ah*Bh.

__device__ __forceinline__ void mma_tf32(float* c, const uint32_t* a, const uint32_t* b) {
    asm volatile(
        "mma.sync.aligned.m16n8k8.row.col.f32.tf32.tf32.f32 "
        "{%0,%1,%2,%3},{%4,%5,%6,%7},{%8,%9},{%0,%1,%2,%3};"
        : "+f"(c[0]), "+f"(c[1]), "+f"(c[2]), "+f"(c[3])
        : "r"(a[0]), "r"(a[1]), "r"(a[2]), "r"(a[3]), "r"(b[0]), "r"(b[1]));
}

__device__ __forceinline__ void split_tf32(float x, float& hi, float& lo) {
    uint32_t h;
    asm("cvt.rna.tf32.f32 %0, %1;" : "=r"(h) : "f"(x));
    float hf = __uint_as_float(h);
    float l = x - hf;
    uint32_t lt;
    asm("cvt.rna.tf32.f32 %0, %1;" : "=r"(lt) : "f"(l));
    hi = hf;
    lo = __uint_as_float(lt);
}

#define KC 32
#define LDA 36
#define LDB 136

__global__ void __launch_bounds__(256, 1)
sgemm_tc(const float* __restrict__ Ain, const float* __restrict__ B, int M, int which) {
    const float* __restrict__ A = which ? g_x1 : Ain;
    float* __restrict__ C = which ? g_xw2 : g_xw1;

    __shared__ float As_hi[128][LDA];
    __shared__ float As_lo[128][LDA];
    __shared__ float Bs_hi[KC][LDB];
    __shared__ float Bs_lo[KC][LDB];

    int tid = threadIdx.x;
    int w = tid >> 5, lane = tid & 31;
    int wm = (w & 1) * 64, wn = (w >> 1) * 32;
    int g = lane >> 2, tig = lane & 3;
    int blockRow = blockIdx.x * 128, blockCol = blockIdx.y * 128;

    float acc[4][4][4];
#pragma unroll
    for (int mt = 0; mt < 4; mt++)
#pragma unroll
        for (int nt = 0; nt < 4; nt++)
#pragma unroll
            for (int q = 0; q < 4; q++) acc[mt][nt][q] = 0.0f;

    int arow = tid >> 1;            // 0..127
    int acol = (tid & 1) * 16;      // 0 / 16
    int brow = tid >> 3;            // 0..31
    int bcol = (tid & 7) * 16;      // 0..112

    for (int k0 = 0; k0 < DD; k0 += KC) {
        float4 av[4], bv[4];
        int gr = blockRow + arow;
#pragma unroll
        for (int i = 0; i < 4; i++) {
            av[i] = (gr < M) ? *(const float4*)(A + (size_t)gr * DD + k0 + acol + i * 4)
                             : make_float4(0.f, 0.f, 0.f, 0.f);
            bv[i] = *(const float4*)(B + (size_t)(k0 + brow) * DD + blockCol + bcol + i * 4);
        }
        __syncthreads();
#pragma unroll
        for (int i = 0; i < 4; i++) {
            float h, l;
            const float* pa = (const float*)&av[i];
            const float* pb = (const float*)&bv[i];
#pragma unroll
            for (int j = 0; j < 4; j++) {
                split_tf32(pa[j], h, l);
                As_hi[arow][acol + i * 4 + j] = h;
                As_lo[arow][acol + i * 4 + j] = l;
                split_tf32(pb[j], h, l);
                Bs_hi[brow][bcol + i * 4 + j] = h;
                Bs_lo[brow][bcol + i * 4 + j] = l;
            }
        }
        __syncthreads();

#pragma unroll
        for (int kk = 0; kk < KC; kk += 8) {
            uint32_t ah[4][4], al[4][4], bh[4][2], bl[4][2];
#pragma unroll
            for (int mt = 0; mt < 4; mt++) {
                int r0 = wm + mt * 16 + g, r1 = r0 + 8;
                int c0 = kk + tig, c1 = c0 + 4;
                ah[mt][0] = __float_as_uint(As_hi[r0][c0]);
                ah[mt][1] = __float_as_uint(As_hi[r1][c0]);
                ah[mt][2] = __float_as_uint(As_hi[r0][c1]);
                ah[mt][3] = __float_as_uint(As_hi[r1][c1]);
                al[mt][0] = __float_as_uint(As_lo[r0][c0]);
                al[mt][1] = __float_as_uint(As_lo[r1][c0]);
                al[mt][2] = __float_as_uint(As_lo[r0][c1]);
                al[mt][3] = __float_as_uint(As_lo[r1][c1]);
            }
#pragma unroll
            for (int nt = 0; nt < 4; nt++) {
                int col = wn + nt * 8 + g;
                bh[nt][0] = __float_as_uint(Bs_hi[kk + tig][col]);
                bh[nt][1] = __float_as_uint(Bs_hi[kk + tig + 4][col]);
                bl[nt][0] = __float_as_uint(Bs_lo[kk + tig][col]);
                bl[nt][1] = __float_as_uint(Bs_lo[kk + tig + 4][col]);
            }
#pragma unroll
            for (int mt = 0; mt < 4; mt++)
#pragma unroll
                for (int nt = 0; nt < 4; nt++) {
                    mma_tf32(acc[mt][nt], al[mt], bh[nt]);   // small terms first
                    mma_tf32(acc[mt][nt], ah[mt], bl[nt]);
                    mma_tf32(acc[mt][nt], ah[mt], bh[nt]);
                }
        }
        __syncthreads();
    }

    // epilogue: c0,c1 at (g, 2tig/2tig+1), c2,c3 at (g+8, ...)
#pragma unroll
    for (int mt = 0; mt < 4; mt++) {
        int r0 = blockRow + wm + mt * 16 + g;
        int r1 = r0 + 8;
#pragma unroll
        for (int nt = 0; nt < 4; nt++) {
            int col = blockCol + wn + nt * 8 + 2 * tig;
            if (r0 < M) *(float2*)(C + (size_t)r0 * DD + col) = make_float2(acc[mt][nt][0], acc[mt][nt][1]);
            if (r1 < M) *(float2*)(C + (size_t)r1 * DD + col) = make_float2(acc[mt][nt][2], acc[mt][nt][3]);
        }
    }
}

// ---------------- GCN aggregation: warp per node ---------------------------
__global__ void gcn_agg(const float* __restrict__ b1, int n) {
    int warp = (blockIdx.x * blockDim.x + threadIdx.x) >> 5;
    if (warp >= n) return;
    int lane = threadIdx.x & 31;
    float di = g_dinv[warp];
    int s = g_rowptr[warp], e = g_rowptr[warp + 1];
    float4 acc0 = make_float4(0.f, 0.f, 0.f, 0.f);
    float4 acc1 = make_float4(0.f, 0.f, 0.f, 0.f);
    for (int i = s; i < e; i++) {
        int src = g_srcs[i];                     // broadcast
        float w = di * g_dinv[src];
        const float4* p = (const float4*)(g_xw1 + (size_t)src * DD);
        float4 v0 = p[lane];
        float4 v1 = p[lane + 32];
        acc0.x += w * v0.x; acc0.y += w * v0.y; acc0.z += w * v0.z; acc0.w += w * v0.w;
        acc1.x += w * v1.x; acc1.y += w * v1.y; acc1.z += w * v1.z; acc1.w += w * v1.w;
    }
    const float4* bb = (const float4*)b1;
    float4 b0 = bb[lane], b1v = bb[lane + 32];
    float4 o0 = make_float4(fmaxf(acc0.x + b0.x, 0.f), fmaxf(acc0.y + b0.y, 0.f),
                            fmaxf(acc0.z + b0.z, 0.f), fmaxf(acc0.w + b0.w, 0.f));
    float4 o1 = make_float4(fmaxf(acc1.x + b1v.x, 0.f), fmaxf(acc1.y + b1v.y, 0.f),
                            fmaxf(acc1.z + b1v.z, 0.f), fmaxf(acc1.w + b1v.w, 0.f));
    float4* out = (float4*)(g_x1 + (size_t)warp * DD);
    out[lane] = o0;
    out[lane + 32] = o1;
}

// ---------------- attention dot products: warp per node --------------------
__global__ void att_dots(const float* __restrict__ att_src,
                         const float* __restrict__ att_dst, int n) {
    int warp = (blockIdx.x * blockDim.x + threadIdx.x) >> 5;
    if (warp >= n) return;
    int lane = threadIdx.x & 31;
    const float4* x = (const float4*)(g_xw2 + (size_t)warp * DD);
    const float4* a = (const float4*)att_src;
    const float4* b = (const float4*)att_dst;
    float ss = 0.f, dd = 0.f;
#pragma unroll
    for (int j = 0; j < 2; j++) {
        float4 v = x[lane + 32 * j];
        float4 va = a[lane + 32 * j];
        float4 vb = b[lane + 32 * j];
        ss += v.x * va.x + v.y * va.y + v.z * va.z + v.w * va.w;
        dd += v.x * vb.x + v.y * vb.y + v.z * vb.z + v.w * vb.w;
    }
#pragma unroll
    for (int off = 16; off > 0; off >>= 1) {
        ss += __shfl_xor_sync(0xffffffffu, ss, off);
        dd += __shfl_xor_sync(0xffffffffu, dd, off);
    }
    if (lane == 0) {
        g_as[warp] = ss;
        g_ad[warp] = dd;
    }
}

// ---------------- GAT aggregation: warp per node ---------------------------
__global__ void gat_agg(const float* __restrict__ b2, float* __restrict__ out, int n) {
    int warp = (blockIdx.x * blockDim.x + threadIdx.x) >> 5;
    if (warp >= n) return;
    int lane = threadIdx.x & 31;
    int s = g_rowptr[warp], e = g_rowptr[warp + 1];
    float ad_n = g_ad[warp];

    // pass 1: per-lane online softmax stats over strided edges
    float m = -INFINITY, sum = 0.f;
    for (int i = s + lane; i < e; i += 32) {
        int src = g_srcs[i];
        float ev = g_as[src] + ad_n;
        ev = (ev >= 0.f) ? ev : 0.2f * ev;
        if (ev > m) {
            sum = sum * expf(m - ev) + 1.0f;
            m = ev;
        } else {
            sum += expf(ev - m);
        }
    }
#pragma unroll
    for (int off = 16; off > 0; off >>= 1) {
        float mo = __shfl_xor_sync(0xffffffffu, m, off);
        float so = __shfl_xor_sync(0xffffffffu, sum, off);
        float mn = fmaxf(m, mo);
        float sa = (m == mn) ? sum : sum * expf(m - mn);
        float sb = (mo == mn) ? so : so * expf(mo - mn);
        sum = sa + sb;
        m = mn;
    }
    float inv = 1.0f / (sum + 1e-16f);

    // pass 2: weighted accumulate (all lanes recompute the scalar edge weight)
    float4 acc0 = make_float4(0.f, 0.f, 0.f, 0.f);
    float4 acc1 = make_float4(0.f, 0.f, 0.f, 0.f);
    for (int i = s; i < e; i++) {
        int src = g_srcs[i];                     // broadcast
        float ev = g_as[src] + ad_n;
        ev = (ev >= 0.f) ? ev : 0.2f * ev;
        float w = expf(ev - m) * inv;
        const float4* p = (const float4*)(g_xw2 + (size_t)src * DD);
        float4 v0 = p[lane];
        float4 v1 = p[lane + 32];
        acc0.x += w * v0.x; acc0.y += w * v0.y; acc0.z += w * v0.z; acc0.w += w * v0.w;
        acc1.x += w * v1.x; acc1.y += w * v1.y; acc1.z += w * v1.z; acc1.w += w * v1.w;
    }
    const float4* bb = (const float4*)b2;
    float4 b0 = bb[lane], b1v = bb[lane + 32];
    float4 o0 = make_float4(fmaxf(acc0.x + b0.x, 0.f), fmaxf(acc0.y + b0.y, 0.f),
                            fmaxf(acc0.z + b0.z, 0.f), fmaxf(acc0.w + b0.w, 0.f));
    float4 o1 = make_float4(fmaxf(acc1.x + b1v.x, 0.f), fmaxf(acc1.y + b1v.y, 0.f),
                            fmaxf(acc1.z + b1v.z, 0.f), fmaxf(acc1.w + b1v.w, 0.f));
    float4* op = (float4*)(out + (size_t)warp * DD);
    op[lane] = o0;
    op[lane + 32] = o1;
}

// ---------------- launch ----------------------------------------------------
static cudaStream_t s_side = nullptr;
static cudaEvent_t ev_fork = nullptr, ev_join = nullptr;

extern "C" void kernel_launch(void* const* d_in, const int* in_sizes, int n_in,
                              void* d_out, int out_size) {
    const float* x       = (const float*)d_in[0];   // [N,256]
    const int*   ei      = (const int*)  d_in[1];   // [2,E]
    const float* W1      = (const float*)d_in[2];   // [256,256]
    const float* b1      = (const float*)d_in[3];   // [256]
    const float* W2      = (const float*)d_in[4];   // [256,256]
    const float* att_src = (const float*)d_in[5];   // [256]
    const float* att_dst = (const float*)d_in[6];   // [256]
    const float* b2      = (const float*)d_in[7];   // [256]
    float* out = (float*)d_out;

    int n = in_sizes[0] / DD;
    int E = in_sizes[1] / 2;
    if (n > N_MAX) n = N_MAX;
    if (E > E_MAX) E = E_MAX;
    const int* src = ei;
    const int* dst = ei + E;
    int nb = (n + 255) / 256;

    if (!s_side) {   // first call is the (non-capture) correctness run
        cudaStreamCreateWithFlags(&s_side, cudaStreamNonBlocking);
        cudaEventCreateWithFlags(&ev_fork, cudaEventDisableTiming);
        cudaEventCreateWithFlags(&ev_join, cudaEventDisableTiming);
    }

    dim3 ggrid((n + 127) / 128, 2);

    // fork: CSR build on side stream, GEMM1 on main stream (independent)
    cudaEventRecord(ev_fork, 0);
    cudaStreamWaitEvent(s_side, ev_fork, 0);

    k_init_cnt<<<(n + 255) / 256, 256, 0, s_side>>>(n);
    k_count<<<(E + 255) / 256, 256, 0, s_side>>>(dst, E);
    k_scan1<<<nb, 256, 0, s_side>>>(n);
    k_scan2<<<1, 32, 0, s_side>>>(nb, n);
    k_scan3_self<<<(n + 255) / 256, 256, 0, s_side>>>(n);
    k_scatter<<<(E + 255) / 256, 256, 0, s_side>>>(src, dst, E);
    cudaEventRecord(ev_join, s_side);

    sgemm_tc<<<ggrid, 256>>>(x, W1, n, 0);                 // g_xw1 = x @ W1

    cudaStreamWaitEvent(0, ev_join, 0);                    // join before agg

    gcn_agg<<<(n + 7) / 8, 256>>>(b1, n);                  // g_x1 = relu(GCN)
    sgemm_tc<<<ggrid, 256>>>(x, W2, n, 1);                 // g_xw2 = g_x1 @ W2
    att_dots<<<(n + 7) / 8, 256>>>(att_src, att_dst, n);
    gat_agg<<<(n + 7) / 8, 256>>>(b2, out, n);             // out = relu(GAT)
}

// round 6
// speedup vs baseline: 1.4626x; 1.4148x over previous
#include <cuda_runtime.h>
#include <cuda_bf16.h>
#include <math.h>
#include <stdint.h>

#define DD 256
#define N_MAX 10000
#define E_MAX 320000
#define ET_MAX (E_MAX + N_MAX)
#define NB_MAX 64

// ---------------- scratch (device globals; no allocation allowed) ----------
__device__ float g_xw1[N_MAX * DD];   // x @ W1
__device__ float g_x1 [N_MAX * DD];   // relu(GCN out)  (layer-2 input)
__device__ float g_xw2[N_MAX * DD];   // x1 @ W2
__device__ float g_as[N_MAX];         // xw2 . att_src  (per node)
__device__ float g_ad[N_MAX];         // xw2 . att_dst
__device__ float g_dinv[N_MAX];       // rsqrt(deg)
__device__ int   g_cnt[N_MAX];        // in-degree incl self loop
__device__ int   g_rowptr[N_MAX + 1];
__device__ int   g_wp[N_MAX];         // write cursors
__device__ int   g_srcs[ET_MAX];      // CSR(src) sorted by dst
__device__ int   g_bsum[NB_MAX];
__device__ int   g_boff[NB_MAX];

// ---------------- CSR build -------------------------------------------------
__global__ void k_init_cnt(int n) {
    int i = blockIdx.x * blockDim.x + threadIdx.x;
    if (i < n) g_cnt[i] = 1;   // self loop
}

__global__ void k_count(const int* __restrict__ dst, int E) {
    int e = blockIdx.x * blockDim.x + threadIdx.x;
    if (e < E) atomicAdd(&g_cnt[dst[e]], 1);
}

__global__ void k_scan1(int n) {
    int i = blockIdx.x * 256 + threadIdx.x;
    int c = (i < n) ? g_cnt[i] : 0;
    if (i < n) g_dinv[i] = rsqrtf((float)c);
    int lane = threadIdx.x & 31, w = threadIdx.x >> 5;
    int v = c;
#pragma unroll
    for (int o = 1; o < 32; o <<= 1) {
        int t = __shfl_up_sync(0xffffffffu, v, o);
        if (lane >= o) v += t;
    }
    __shared__ int ws[8];
    if (lane == 31) ws[w] = v;
    __syncthreads();
    if (w == 0 && lane < 8) {
        int s = ws[lane];
#pragma unroll
        for (int o = 1; o < 8; o <<= 1) {
            int t = __shfl_up_sync(0xffu, s, o);
            if (lane >= o) s += t;
        }
        ws[lane] = s;
    }
    __syncthreads();
    int excl = v - c + (w ? ws[w - 1] : 0);
    if (i < n) g_rowptr[i] = excl;
    if (threadIdx.x == 0) g_bsum[blockIdx.x] = ws[7];
}

__global__ void k_scan2(int nb, int n) {
    int lane = threadIdx.x;
    int v0 = (lane < nb) ? g_bsum[lane] : 0;
    int v1 = (lane + 32 < nb) ? g_bsum[lane + 32] : 0;
    int s0 = v0, s1 = v1;
#pragma unroll
    for (int o = 1; o < 32; o <<= 1) {
        int t = __shfl_up_sync(0xffffffffu, s0, o);
        if (lane >= o) s0 += t;
        int t1 = __shfl_up_sync(0xffffffffu, s1, o);
        if (lane >= o) s1 += t1;
    }
    int tot0 = __shfl_sync(0xffffffffu, s0, 31);
    s1 += tot0;
    g_boff[lane] = s0 - v0;
    g_boff[lane + 32] = s1 - v1;
    if (lane == 31) g_rowptr[n] = s1;
}

__global__ void k_scan3_self(int n) {
    int i = blockIdx.x * blockDim.x + threadIdx.x;
    if (i < n) {
        int p = g_rowptr[i] + g_boff[i >> 8];
        g_rowptr[i] = p;
        g_srcs[p] = i;       // self loop first
        g_wp[i] = p + 1;
    }
}

__global__ void k_scatter(const int* __restrict__ src, const int* __restrict__ dst, int E) {
    int e = blockIdx.x * blockDim.x + threadIdx.x;
    if (e < E) {
        int d = dst[e];
        int pos = atomicAdd(&g_wp[d], 1);
        g_srcs[pos] = src[e];
    }
}

// ---------------- bf16x3 tensor GEMM: C[M,256]=A[M,256]@B[256,256] ---------
// block tile 128x64, 8 warps (2m x 4n), warp tile 64x16, mma m16n8k16 bf16.
// fp32 = hi_bf16 + lo_bf16; D += Al*Bh + Ah*Bl + Ah*Bh (fp32 accumulate).

__device__ __forceinline__ void mma_bf16(float* c, const uint32_t* a, const uint32_t* b) {
    asm volatile(
        "mma.sync.aligned.m16n8k16.row.col.f32.bf16.bf16.f32 "
        "{%0,%1,%2,%3},{%4,%5,%6,%7},{%8,%9},{%0,%1,%2,%3};"
        : "+f"(c[0]), "+f"(c[1]), "+f"(c[2]), "+f"(c[3])
        : "r"(a[0]), "r"(a[1]), "r"(a[2]), "r"(a[3]), "r"(b[0]), "r"(b[1]));
}

// split two fp32 into packed bf16x2 hi and lo (element0 in low half)
__device__ __forceinline__ void split2(float x0, float x1, uint32_t& hi, uint32_t& lo) {
    __nv_bfloat162 h = __floats2bfloat162_rn(x0, x1);
    float2 hf = __bfloat1622float2(h);
    __nv_bfloat162 l = __floats2bfloat162_rn(x0 - hf.x, x1 - hf.y);
    hi = *(uint32_t*)&h;
    lo = *(uint32_t*)&l;
}

#define KC 32
#define LDA 20   // u32 stride for A smem rows (16 kpairs + pad) -> conflict-free frag reads
#define LDB 17   // u32 stride for B smem cols (<=2-way both directions)

__global__ void __launch_bounds__(256, 2)
sgemm_tc(const float* __restrict__ Ain, const float* __restrict__ B, int M, int which) {
    const float* __restrict__ A = which ? g_x1 : Ain;
    float* __restrict__ C = which ? g_xw2 : g_xw1;

    __shared__ uint32_t As_hi[128][LDA];   // [row][kpair]
    __shared__ uint32_t As_lo[128][LDA];
    __shared__ uint32_t Bs_hi[64][LDB];    // [col][kpair]
    __shared__ uint32_t Bs_lo[64][LDB];

    int tid = threadIdx.x;
    int w = tid >> 5, lane = tid & 31;
    int wm = (w & 1) * 64;
    int wn = (w >> 1) * 16;
    int g = lane >> 2, tig = lane & 3;
    int blockRow = blockIdx.x * 128, blockCol = blockIdx.y * 64;

    float acc[4][2][4];
#pragma unroll
    for (int mt = 0; mt < 4; mt++)
#pragma unroll
        for (int nt = 0; nt < 2; nt++)
#pragma unroll
            for (int q = 0; q < 4; q++) acc[mt][nt][q] = 0.0f;

    // A staging: 128 rows x 32 k floats; thread -> row tid>>1, k half (tid&1)*16
    int arow = tid >> 1;
    int acol = (tid & 1) * 16;
    // B staging: 32 k x 64 n floats; thread -> 2 k-rows, 4 cols
    int bk = (tid >> 4) * 2;        // 0..30 even
    int bn = (tid & 15) * 4;        // 0..60

    for (int k0 = 0; k0 < DD; k0 += KC) {
        // ---- load + split A ----
        int gr = blockRow + arow;
#pragma unroll
        for (int i = 0; i < 4; i++) {
            float4 v = (gr < M) ? *(const float4*)(A + (size_t)gr * DD + k0 + acol + i * 4)
                                : make_float4(0.f, 0.f, 0.f, 0.f);
            uint32_t h0, l0, h1, l1;
            split2(v.x, v.y, h0, l0);
            split2(v.z, v.w, h1, l1);
            int kp = (acol + i * 4) >> 1;
            As_hi[arow][kp] = h0;  As_lo[arow][kp] = l0;
            As_hi[arow][kp + 1] = h1;  As_lo[arow][kp + 1] = l1;
        }
        // ---- load + split B (transpose to [col][kpair]) ----
        {
            const float* brow0 = B + (size_t)(k0 + bk) * DD + blockCol + bn;
            float4 r0 = *(const float4*)brow0;
            float4 r1 = *(const float4*)(brow0 + DD);
            int kp = bk >> 1;
            uint32_t h, l;
            split2(r0.x, r1.x, h, l); Bs_hi[bn + 0][kp] = h; Bs_lo[bn + 0][kp] = l;
            split2(r0.y, r1.y, h, l); Bs_hi[bn + 1][kp] = h; Bs_lo[bn + 1][kp] = l;
            split2(r0.z, r1.z, h, l); Bs_hi[bn + 2][kp] = h; Bs_lo[bn + 2][kp] = l;
            split2(r0.w, r1.w, h, l); Bs_hi[bn + 3][kp] = h; Bs_lo[bn + 3][kp] = l;
        }
        __syncthreads();

#pragma unroll
        for (int kk = 0; kk < KC; kk += 16) {
            int kb = kk >> 1;   // kpair base: 0 or 8
            uint32_t ah[4][4], al[4][4], bh[2][2], bl[2][2];
#pragma unroll
            for (int mt = 0; mt < 4; mt++) {
                int r0 = wm + mt * 16 + g, r1 = r0 + 8;
                ah[mt][0] = As_hi[r0][kb + tig];
                ah[mt][1] = As_hi[r1][kb + tig];
                ah[mt][2] = As_hi[r0][kb + tig + 4];
                ah[mt][3] = As_hi[r1][kb + tig + 4];
                al[mt][0] = As_lo[r0][kb + tig];
                al[mt][1] = As_lo[r1][kb + tig];
                al[mt][2] = As_lo[r0][kb + tig + 4];
                al[mt][3] = As_lo[r1][kb + tig + 4];
            }
#pragma unroll
            for (int nt = 0; nt < 2; nt++) {
                int col = wn + nt * 8 + g;
                bh[nt][0] = Bs_hi[col][kb + tig];
                bh[nt][1] = Bs_hi[col][kb + tig + 4];
                bl[nt][0] = Bs_lo[col][kb + tig];
                bl[nt][1] = Bs_lo[col][kb + tig + 4];
            }
#pragma unroll
            for (int mt = 0; mt < 4; mt++)
#pragma unroll
                for (int nt = 0; nt < 2; nt++) {
                    mma_bf16(acc[mt][nt], al[mt], bh[nt]);   // small terms first
                    mma_bf16(acc[mt][nt], ah[mt], bl[nt]);
                    mma_bf16(acc[mt][nt], ah[mt], bh[nt]);
                }
        }
        __syncthreads();
    }

#pragma unroll
    for (int mt = 0; mt < 4; mt++) {
        int r0 = blockRow + wm + mt * 16 + g;
        int r1 = r0 + 8;
#pragma unroll
        for (int nt = 0; nt < 2; nt++) {
            int col = blockCol + wn + nt * 8 + 2 * tig;
            if (r0 < M) *(float2*)(C + (size_t)r0 * DD + col) = make_float2(acc[mt][nt][0], acc[mt][nt][1]);
            if (r1 < M) *(float2*)(C + (size_t)r1 * DD + col) = make_float2(acc[mt][nt][2], acc[mt][nt][3]);
        }
    }
}

// ---------------- GCN aggregation: warp per node, 2-edge unrolled ----------
__global__ void gcn_agg(const float* __restrict__ b1, int n) {
    int warp = (blockIdx.x * blockDim.x + threadIdx.x) >> 5;
    if (warp >= n) return;
    int lane = threadIdx.x & 31;
    float di = g_dinv[warp];
    int s = g_rowptr[warp], e = g_rowptr[warp + 1];
    float4 acc0 = make_float4(0.f, 0.f, 0.f, 0.f);
    float4 acc1 = make_float4(0.f, 0.f, 0.f, 0.f);
    int i = s;
    for (; i + 2 <= e; i += 2) {
        int s0 = g_srcs[i], s1 = g_srcs[i + 1];
        float w0 = di * g_dinv[s0];
        float w1 = di * g_dinv[s1];
        const float4* p0 = (const float4*)(g_xw1 + (size_t)s0 * DD);
        const float4* p1 = (const float4*)(g_xw1 + (size_t)s1 * DD);
        float4 a0 = p0[lane], a1 = p0[lane + 32];
        float4 c0 = p1[lane], c1 = p1[lane + 32];
        acc0.x += w0 * a0.x + w1 * c0.x; acc0.y += w0 * a0.y + w1 * c0.y;
        acc0.z += w0 * a0.z + w1 * c0.z; acc0.w += w0 * a0.w + w1 * c0.w;
        acc1.x += w0 * a1.x + w1 * c1.x; acc1.y += w0 * a1.y + w1 * c1.y;
        acc1.z += w0 * a1.z + w1 * c1.z; acc1.w += w0 * a1.w + w1 * c1.w;
    }
    if (i < e) {
        int s0 = g_srcs[i];
        float w0 = di * g_dinv[s0];
        const float4* p0 = (const float4*)(g_xw1 + (size_t)s0 * DD);
        float4 a0 = p0[lane], a1 = p0[lane + 32];
        acc0.x += w0 * a0.x; acc0.y += w0 * a0.y; acc0.z += w0 * a0.z; acc0.w += w0 * a0.w;
        acc1.x += w0 * a1.x; acc1.y += w0 * a1.y; acc1.z += w0 * a1.z; acc1.w += w0 * a1.w;
    }
    const float4* bb = (const float4*)b1;
    float4 b0 = bb[lane], b1v = bb[lane + 32];
    float4 o0 = make_float4(fmaxf(acc0.x + b0.x, 0.f), fmaxf(acc0.y + b0.y, 0.f),
                            fmaxf(acc0.z + b0.z, 0.f), fmaxf(acc0.w + b0.w, 0.f));
    float4 o1 = make_float4(fmaxf(acc1.x + b1v.x, 0.f), fmaxf(acc1.y + b1v.y, 0.f),
                            fmaxf(acc1.z + b1v.z, 0.f), fmaxf(acc1.w + b1v.w, 0.f));
    float4* out = (float4*)(g_x1 + (size_t)warp * DD);
    out[lane] = o0;
    out[lane + 32] = o1;
}

// ---------------- attention dot products: warp per node --------------------
__global__ void att_dots(const float* __restrict__ att_src,
                         const float* __restrict__ att_dst, int n) {
    int warp = (blockIdx.x * blockDim.x + threadIdx.x) >> 5;
    if (warp >= n) return;
    int lane = threadIdx.x & 31;
    const float4* x = (const float4*)(g_xw2 + (size_t)warp * DD);
    const float4* a = (const float4*)att_src;
    const float4* b = (const float4*)att_dst;
    float ss = 0.f, dd = 0.f;
#pragma unroll
    for (int j = 0; j < 2; j++) {
        float4 v = x[lane + 32 * j];
        float4 va = a[lane + 32 * j];
        float4 vb = b[lane + 32 * j];
        ss += v.x * va.x + v.y * va.y + v.z * va.z + v.w * va.w;
        dd += v.x * vb.x + v.y * vb.y + v.z * vb.z + v.w * vb.w;
    }
#pragma unroll
    for (int off = 16; off > 0; off >>= 1) {
        ss += __shfl_xor_sync(0xffffffffu, ss, off);
        dd += __shfl_xor_sync(0xffffffffu, dd, off);
    }
    if (lane == 0) {
        g_as[warp] = ss;
        g_ad[warp] = dd;
    }
}

// ---------------- GAT aggregation: warp per node ---------------------------
__global__ void gat_agg(const float* __restrict__ b2, float* __restrict__ out, int n) {
    int warp = (blockIdx.x * blockDim.x + threadIdx.x) >> 5;
    if (warp >= n) return;
    int lane = threadIdx.x & 31;
    int s = g_rowptr[warp], e = g_rowptr[warp + 1];
    float ad_n = g_ad[warp];

    // pass 1: per-lane online softmax stats
    float m = -INFINITY, sum = 0.f;
    for (int i = s + lane; i < e; i += 32) {
        int src = g_srcs[i];
        float ev = g_as[src] + ad_n;
        ev = (ev >= 0.f) ? ev : 0.2f * ev;
        if (ev > m) {
            sum = sum * expf(m - ev) + 1.0f;
            m = ev;
        } else {
            sum += expf(ev - m);
        }
    }
#pragma unroll
    for (int off = 16; off > 0; off >>= 1) {
        float mo = __shfl_xor_sync(0xffffffffu, m, off);
        float so = __shfl_xor_sync(0xffffffffu, sum, off);
        float mn = fmaxf(m, mo);
        float sa = (m == mn) ? sum : sum * expf(m - mn);
        float sb = (mo == mn) ? so : so * expf(mo - mn);
        sum = sa + sb;
        m = mn;
    }
    float inv = 1.0f / (sum + 1e-16f);

    // pass 2: weighted accumulate, 2-edge unrolled
    float4 acc0 = make_float4(0.f, 0.f, 0.f, 0.f);
    float4 acc1 = make_float4(0.f, 0.f, 0.f, 0.f);
    int i = s;
    for (; i + 2 <= e; i += 2) {
        int s0 = g_srcs[i], s1 = g_srcs[i + 1];
        float e0 = g_as[s0] + ad_n;
        float e1 = g_as[s1] + ad_n;
        e0 = (e0 >= 0.f) ? e0 : 0.2f * e0;
        e1 = (e1 >= 0.f) ? e1 : 0.2f * e1;
        float w0 = expf(e0 - m) * inv;
        float w1 = expf(e1 - m) * inv;
        const float4* p0 = (const float4*)(g_xw2 + (size_t)s0 * DD);
        const float4* p1 = (const float4*)(g_xw2 + (size_t)s1 * DD);
        float4 a0 = p0[lane], a1 = p0[lane + 32];
        float4 c0 = p1[lane], c1 = p1[lane + 32];
        acc0.x += w0 * a0.x + w1 * c0.x; acc0.y += w0 * a0.y + w1 * c0.y;
        acc0.z += w0 * a0.z + w1 * c0.z; acc0.w += w0 * a0.w + w1 * c0.w;
        acc1.x += w0 * a1.x + w1 * c1.x; acc1.y += w0 * a1.y + w1 * c1.y;
        acc1.z += w0 * a1.z + w1 * c1.z; acc1.w += w0 * a1.w + w1 * c1.w;
    }
    if (i < e) {
        int s0 = g_srcs[i];
        float e0 = g_as[s0] + ad_n;
        e0 = (e0 >= 0.f) ? e0 : 0.2f * e0;
        float w0 = expf(e0 - m) * inv;
        const float4* p0 = (const float4*)(g_xw2 + (size_t)s0 * DD);
        float4 a0 = p0[lane], a1 = p0[lane + 32];
        acc0.x += w0 * a0.x; acc0.y += w0 * a0.y; acc0.z += w0 * a0.z; acc0.w += w0 * a0.w;
        acc1.x += w0 * a1.x; acc1.y += w0 * a1.y; acc1.z += w0 * a1.z; acc1.w += w0 * a1.w;
    }
    const float4* bb = (const float4*)b2;
    float4 b0 = bb[lane], b1v = bb[lane + 32];
    float4 o0 = make_float4(fmaxf(acc0.x + b0.x, 0.f), fmaxf(acc0.y + b0.y, 0.f),
                            fmaxf(acc0.z + b0.z, 0.f), fmaxf(acc0.w + b0.w, 0.f));
    float4 o1 = make_float4(fmaxf(acc1.x + b1v.x, 0.f), fmaxf(acc1.y + b1v.y, 0.f),
                            fmaxf(acc1.z + b1v.z, 0.f), fmaxf(acc1.w + b1v.w, 0.f));
    float4* op = (float4*)(out + (size_t)warp * DD);
    op[lane] = o0;
    op[lane + 32] = o1;
}

// ---------------- launch ----------------------------------------------------
static cudaStream_t s_side = nullptr;
static cudaEvent_t ev_fork = nullptr, ev_join = nullptr;

extern "C" void kernel_launch(void* const* d_in, const int* in_sizes, int n_in,
                              void* d_out, int out_size) {
    const float* x       = (const float*)d_in[0];
    const int*   ei      = (const int*)  d_in[1];
    const float* W1      = (const float*)d_in[2];
    const float* b1      = (const float*)d_in[3];
    const float* W2      = (const float*)d_in[4];
    const float* att_src = (const float*)d_in[5];
    const float* att_dst = (const float*)d_in[6];
    const float* b2      = (const float*)d_in[7];
    float* out = (float*)d_out;

    int n = in_sizes[0] / DD;
    int E = in_sizes[1] / 2;
    if (n > N_MAX) n = N_MAX;
    if (E > E_MAX) E = E_MAX;
    const int* src = ei;
    const int* dst = ei + E;
    int nb = (n + 255) / 256;

    if (!s_side) {   // first call is the (non-capture) correctness run
        cudaStreamCreateWithFlags(&s_side, cudaStreamNonBlocking);
        cudaEventCreateWithFlags(&ev_fork, cudaEventDisableTiming);
        cudaEventCreateWithFlags(&ev_join, cudaEventDisableTiming);
    }

    dim3 ggrid((n + 127) / 128, 4);   // 128x64 tiles over [M,256]

    // fork: CSR build on side stream, GEMM1 on main stream
    cudaEventRecord(ev_fork, 0);
    cudaStreamWaitEvent(s_side, ev_fork, 0);

    k_init_cnt<<<(n + 255) / 256, 256, 0, s_side>>>(n);      // launch 1
    k_count<<<(E + 255) / 256, 256, 0, s_side>>>(dst, E);    // 2
    k_scan1<<<nb, 256, 0, s_side>>>(n);                      // 3
    k_scan2<<<1, 32, 0, s_side>>>(nb, n);                    // 4
    k_scan3_self<<<(n + 255) / 256, 256, 0, s_side>>>(n);    // 5

    sgemm_tc<<<ggrid, 256>>>(x, W1, n, 0);                   // 6 (profiled)

    k_scatter<<<(E + 255) / 256, 256, 0, s_side>>>(src, dst, E);  // 7
    cudaEventRecord(ev_join, s_side);
    cudaStreamWaitEvent(0, ev_join, 0);

    gcn_agg<<<(n + 7) / 8, 256>>>(b1, n);                    // 8
    sgemm_tc<<<ggrid, 256>>>(x, W2, n, 1);                   // 9
    att_dots<<<(n + 7) / 8, 256>>>(att_src, att_dst, n);     // 10
    gat_agg<<<(n + 7) / 8, 256>>>(b2, out, n);               // 11
}

// round 9
// speedup vs baseline: 1.5157x; 1.0363x over previous
#include <cuda_runtime.h>
#include <cuda_bf16.h>
#include <math.h>
#include <stdint.h>

#define DD 256
#define N_MAX 10000
#define NPAD 10112            // 79 * 128, covers last GEMM tile rows
#define E_MAX 320000
#define ET_MAX (E_MAX + N_MAX)
#define NB_MAX 64

// ---------------- scratch (device globals; no allocation allowed) ----------
__device__ float g_xw1[N_MAX * DD];        // x @ W1 (fp32, read by gcn_agg)
__device__ float g_xw2[N_MAX * DD];        // x1 @ W2 (fp32, read by gat_agg)
__device__ uint32_t g_Ahi[NPAD * 128];     // x split, packed bf16x2 [row][kpair]
__device__ uint32_t g_Alo[NPAD * 128];
__device__ uint32_t g_x1hi[NPAD * 128];    // relu(GCN) split, packed
__device__ uint32_t g_x1lo[NPAD * 128];
__device__ uint32_t g_B1hi[256 * 128];     // W1 split, packed [col][kpair]
__device__ uint32_t g_B1lo[256 * 128];
__device__ uint32_t g_B2hi[256 * 128];     // W2 split
__device__ uint32_t g_B2lo[256 * 128];
__device__ float g_as[N_MAX];              // xw2 . att_src  (per node)
__device__ float g_ad[N_MAX];              // xw2 . att_dst
__device__ float g_dinv[N_MAX];
__device__ int   g_cnt[N_MAX];
__device__ int   g_rowptr[N_MAX + 1];
__device__ int   g_wp[N_MAX];
__device__ int   g_srcs[ET_MAX];
__device__ int   g_bsum[NB_MAX];
__device__ int   g_boff[NB_MAX];

// split two fp32 into packed bf16x2 hi and lo (element0 in low half)
__device__ __forceinline__ void split2(float x0, float x1, uint32_t& hi, uint32_t& lo) {
    __nv_bfloat162 h = __floats2bfloat162_rn(x0, x1);
    float2 hf = __bfloat1622float2(h);
    __nv_bfloat162 l = __floats2bfloat162_rn(x0 - hf.x, x1 - hf.y);
    hi = *(uint32_t*)&h;
    lo = *(uint32_t*)&l;
}

// ---------------- CSR build -------------------------------------------------
__global__ void k_init_cnt(int n) {
    int i = blockIdx.x * blockDim.x + threadIdx.x;
    if (i < n) g_cnt[i] = 1;
}

__global__ void k_count(const int* __restrict__ dst, int E) {
    int e = blockIdx.x * blockDim.x + threadIdx.x;
    if (e < E) atomicAdd(&g_cnt[dst[e]], 1);
}

__global__ void k_scan1(int n) {
    int i = blockIdx.x * 256 + threadIdx.x;
    int c = (i < n) ? g_cnt[i] : 0;
    if (i < n) g_dinv[i] = rsqrtf((float)c);
    int lane = threadIdx.x & 31, w = threadIdx.x >> 5;
    int v = c;
#pragma unroll
    for (int o = 1; o < 32; o <<= 1) {
        int t = __shfl_up_sync(0xffffffffu, v, o);
        if (lane >= o) v += t;
    }
    __shared__ int ws[8];
    if (lane == 31) ws[w] = v;
    __syncthreads();
    if (w == 0 && lane < 8) {
        int s = ws[lane];
#pragma unroll
        for (int o = 1; o < 8; o <<= 1) {
            int t = __shfl_up_sync(0xffu, s, o);
            if (lane >= o) s += t;
        }
        ws[lane] = s;
    }
    __syncthreads();
    int excl = v - c + (w ? ws[w - 1] : 0);
    if (i < n) g_rowptr[i] = excl;
    if (threadIdx.x == 0) g_bsum[blockIdx.x] = ws[7];
}

__global__ void k_scan2(int nb, int n) {
    int lane = threadIdx.x;
    int v0 = (lane < nb) ? g_bsum[lane] : 0;
    int v1 = (lane + 32 < nb) ? g_bsum[lane + 32] : 0;
    int s0 = v0, s1 = v1;
#pragma unroll
    for (int o = 1; o < 32; o <<= 1) {
        int t = __shfl_up_sync(0xffffffffu, s0, o);
        if (lane >= o) s0 += t;
        int t1 = __shfl_up_sync(0xffffffffu, s1, o);
        if (lane >= o) s1 += t1;
    }
    int tot0 = __shfl_sync(0xffffffffu, s0, 31);
    s1 += tot0;
    g_boff[lane] = s0 - v0;
    g_boff[lane + 32] = s1 - v1;
    if (lane == 31) g_rowptr[n] = s1;
}

// stage 3: apply offsets + plant self-loop + init cursors + zero att dots
__global__ void k_scan3_self(int n) {
    int i = blockIdx.x * blockDim.x + threadIdx.x;
    if (i < n) {
        int p = g_rowptr[i] + g_boff[i >> 8];
        g_rowptr[i] = p;
        g_srcs[p] = i;
        g_wp[i] = p + 1;
        g_as[i] = 0.0f;      // fused-dot accumulators for layer 2
        g_ad[i] = 0.0f;
    }
}

__global__ void k_scatter(const int* __restrict__ src, const int* __restrict__ dst, int E) {
    int e = blockIdx.x * blockDim.x + threadIdx.x;
    if (e < E) {
        int d = dst[e];
        int pos = atomicAdd(&g_wp[d], 1);
        g_srcs[pos] = src[e];
    }
}

// ---------------- pre-split kernels ----------------------------------------
// x [n,256] fp32 -> g_Ahi/g_Alo packed [row][kpair]
__global__ void k_split_x(const float* __restrict__ x, int n) {
    int i = blockIdx.x * blockDim.x + threadIdx.x;   // over n*64 float4s
    if (i >= n * 64) return;
    float4 v = ((const float4*)x)[i];
    uint2 h, l;
    split2(v.x, v.y, h.x, l.x);
    split2(v.z, v.w, h.y, l.y);
    *(uint2*)&g_Ahi[(size_t)i * 2] = h;
    *(uint2*)&g_Alo[(size_t)i * 2] = l;
}

// W1,W2 [256,256] row-major(k,n) -> packed [n][kpair]
__global__ void k_split_w(const float* __restrict__ W1, const float* __restrict__ W2) {
    int t = blockIdx.x * blockDim.x + threadIdx.x;   // 0..65535
    int sel = t >> 15;
    int u = t & 32767;
    int kp = u >> 8, nn = u & 255;
    const float* W = sel ? W2 : W1;
    uint32_t* oh = sel ? g_B2hi : g_B1hi;
    uint32_t* ol = sel ? g_B2lo : g_B1lo;
    float w0 = W[(2 * kp) * 256 + nn];
    float w1 = W[(2 * kp + 1) * 256 + nn];
    uint32_t h, l;
    split2(w0, w1, h, l);
    oh[nn * 128 + kp] = h;
    ol[nn * 128 + kp] = l;
}

// ---------------- bf16x3 tensor GEMM on pre-split operands -----------------
// block tile 128x64, 8 warps (2m x 4n), mma m16n8k16 bf16, fp32 accum.
// D += Al*Bh + Ah*Bl + Ah*Bh. layer selects operands INSIDE the kernel
// (device globals must not be passed as args from host code).

__device__ __forceinline__ void mma_bf16(float* c, const uint32_t* a, const uint32_t* b) {
    asm volatile(
        "mma.sync.aligned.m16n8k16.row.col.f32.bf16.bf16.f32 "
        "{%0,%1,%2,%3},{%4,%5,%6,%7},{%8,%9},{%0,%1,%2,%3};"
        : "+f"(c[0]), "+f"(c[1]), "+f"(c[2]), "+f"(c[3])
        : "r"(a[0]), "r"(a[1]), "r"(a[2]), "r"(a[3]), "r"(b[0]), "r"(b[1]));
}

#define KC 32
#define LDA 20   // kpair stride + pad -> conflict-free frag reads, 16B-aligned staging
#define LDB 20

__global__ void __launch_bounds__(256, 2)
sgemm_pk(int M, const float* __restrict__ asrc, const float* __restrict__ adst, int layer) {
    const uint32_t* __restrict__ Ahi = layer ? g_x1hi : g_Ahi;
    const uint32_t* __restrict__ Alo = layer ? g_x1lo : g_Alo;
    const uint32_t* __restrict__ Bhi = layer ? g_B2hi : g_B1hi;
    const uint32_t* __restrict__ Blo = layer ? g_B2lo : g_B1lo;
    float* __restrict__ C = layer ? g_xw2 : g_xw1;

    __shared__ uint32_t As_hi[128][LDA];
    __shared__ uint32_t As_lo[128][LDA];
    __shared__ uint32_t Bs_hi[64][LDB];
    __shared__ uint32_t Bs_lo[64][LDB];

    int tid = threadIdx.x;
    int w = tid >> 5, lane = tid & 31;
    int wm = (w & 1) * 64;
    int wn = (w >> 1) * 16;
    int g = lane >> 2, tig = lane & 3;
    int blockRow = blockIdx.x * 128, blockCol = blockIdx.y * 64;

    float acc[4][2][4];
#pragma unroll
    for (int mt = 0; mt < 4; mt++)
#pragma unroll
        for (int nt = 0; nt < 2; nt++)
#pragma unroll
            for (int q = 0; q < 4; q++) acc[mt][nt][q] = 0.0f;

    int arow = tid >> 1;            // 0..127
    int ahalf = (tid & 1) * 8;      // kpair half
    int bcol = tid >> 2;            // 0..63
    int bq = (tid & 3) * 4;         // kpair quarter

    const uint32_t* pa_h = Ahi + (size_t)(blockRow + arow) * 128 + ahalf;
    const uint32_t* pa_l = Alo + (size_t)(blockRow + arow) * 128 + ahalf;
    const uint32_t* pb_h = Bhi + (size_t)(blockCol + bcol) * 128 + bq;
    const uint32_t* pb_l = Blo + (size_t)(blockCol + bcol) * 128 + bq;

    for (int k0 = 0; k0 < DD; k0 += KC) {
        int kp0 = k0 >> 1;
        uint4 ah0 = *(const uint4*)(pa_h + kp0);
        uint4 ah1 = *(const uint4*)(pa_h + kp0 + 4);
        uint4 al0 = *(const uint4*)(pa_l + kp0);
        uint4 al1 = *(const uint4*)(pa_l + kp0 + 4);
        uint4 bhv = *(const uint4*)(pb_h + kp0);
        uint4 blv = *(const uint4*)(pb_l + kp0);
        *(uint4*)&As_hi[arow][ahalf] = ah0;
        *(uint4*)&As_hi[arow][ahalf + 4] = ah1;
        *(uint4*)&As_lo[arow][ahalf] = al0;
        *(uint4*)&As_lo[arow][ahalf + 4] = al1;
        *(uint4*)&Bs_hi[bcol][bq] = bhv;
        *(uint4*)&Bs_lo[bcol][bq] = blv;
        __syncthreads();

#pragma unroll
        for (int kk = 0; kk < KC; kk += 16) {
            int kb = kk >> 1;
            uint32_t ah[4][4], al[4][4], bh[2][2], bl[2][2];
#pragma unroll
            for (int mt = 0; mt < 4; mt++) {
                int r0 = wm + mt * 16 + g, r1 = r0 + 8;
                ah[mt][0] = As_hi[r0][kb + tig];
                ah[mt][1] = As_hi[r1][kb + tig];
                ah[mt][2] = As_hi[r0][kb + tig + 4];
                ah[mt][3] = As_hi[r1][kb + tig + 4];
                al[mt][0] = As_lo[r0][kb + tig];
                al[mt][1] = As_lo[r1][kb + tig];
                al[mt][2] = As_lo[r0][kb + tig + 4];
                al[mt][3] = As_lo[r1][kb + tig + 4];
            }
#pragma unroll
            for (int nt = 0; nt < 2; nt++) {
                int col = wn + nt * 8 + g;
                bh[nt][0] = Bs_hi[col][kb + tig];
                bh[nt][1] = Bs_hi[col][kb + tig + 4];
                bl[nt][0] = Bs_lo[col][kb + tig];
                bl[nt][1] = Bs_lo[col][kb + tig + 4];
            }
#pragma unroll
            for (int mt = 0; mt < 4; mt++)
#pragma unroll
                for (int nt = 0; nt < 2; nt++) {
                    mma_bf16(acc[mt][nt], al[mt], bh[nt]);   // small terms first
                    mma_bf16(acc[mt][nt], ah[mt], bl[nt]);
                    mma_bf16(acc[mt][nt], ah[mt], bh[nt]);
                }
        }
        __syncthreads();
    }

    // ---- store C ----
#pragma unroll
    for (int mt = 0; mt < 4; mt++) {
        int r0 = blockRow + wm + mt * 16 + g;
        int r1 = r0 + 8;
#pragma unroll
        for (int nt = 0; nt < 2; nt++) {
            int col = blockCol + wn + nt * 8 + 2 * tig;
            if (r0 < M) *(float2*)(C + (size_t)r0 * DD + col) = make_float2(acc[mt][nt][0], acc[mt][nt][1]);
            if (r1 < M) *(float2*)(C + (size_t)r1 * DD + col) = make_float2(acc[mt][nt][2], acc[mt][nt][3]);
        }
    }

    // ---- fused attention dot products (layer 2 only) ----
    if (layer) {
#pragma unroll
        for (int mt = 0; mt < 4; mt++) {
            float s0 = 0.f, d0 = 0.f, s1 = 0.f, d1 = 0.f;
#pragma unroll
            for (int nt = 0; nt < 2; nt++) {
                int col = blockCol + wn + nt * 8 + 2 * tig;
                float a0 = asrc[col], a1 = asrc[col + 1];
                float t0 = adst[col], t1 = adst[col + 1];
                s0 += acc[mt][nt][0] * a0 + acc[mt][nt][1] * a1;
                d0 += acc[mt][nt][0] * t0 + acc[mt][nt][1] * t1;
                s1 += acc[mt][nt][2] * a0 + acc[mt][nt][3] * a1;
                d1 += acc[mt][nt][2] * t0 + acc[mt][nt][3] * t1;
            }
#pragma unroll
            for (int off = 1; off <= 2; off <<= 1) {
                s0 += __shfl_xor_sync(0xffffffffu, s0, off);
                d0 += __shfl_xor_sync(0xffffffffu, d0, off);
                s1 += __shfl_xor_sync(0xffffffffu, s1, off);
                d1 += __shfl_xor_sync(0xffffffffu, d1, off);
            }
            if (tig == 0) {
                int r0 = blockRow + wm + mt * 16 + g;
                int r1 = r0 + 8;
                if (r0 < M) { atomicAdd(&g_as[r0], s0); atomicAdd(&g_ad[r0], d0); }
                if (r1 < M) { atomicAdd(&g_as[r1], s1); atomicAdd(&g_ad[r1], d1); }
            }
        }
    }
}

// ---------------- GCN aggregation: warp per node, emits packed bf16 --------
__global__ void gcn_agg(const float* __restrict__ b1, int n) {
    int warp = (blockIdx.x * blockDim.x + threadIdx.x) >> 5;
    if (warp >= n) return;
    int lane = threadIdx.x & 31;
    float di = g_dinv[warp];
    int s = g_rowptr[warp], e = g_rowptr[warp + 1];
    float4 acc0 = make_float4(0.f, 0.f, 0.f, 0.f);
    float4 acc1 = make_float4(0.f, 0.f, 0.f, 0.f);
    int i = s;
    for (; i + 2 <= e; i += 2) {
        int s0 = g_srcs[i], s1 = g_srcs[i + 1];
        float w0 = di * g_dinv[s0];
        float w1 = di * g_dinv[s1];
        const float4* p0 = (const float4*)(g_xw1 + (size_t)s0 * DD);
        const float4* p1 = (const float4*)(g_xw1 + (size_t)s1 * DD);
        float4 a0 = p0[lane], a1 = p0[lane + 32];
        float4 c0 = p1[lane], c1 = p1[lane + 32];
        acc0.x += w0 * a0.x + w1 * c0.x; acc0.y += w0 * a0.y + w1 * c0.y;
        acc0.z += w0 * a0.z + w1 * c0.z; acc0.w += w0 * a0.w + w1 * c0.w;
        acc1.x += w0 * a1.x + w1 * c1.x; acc1.y += w0 * a1.y + w1 * c1.y;
        acc1.z += w0 * a1.z + w1 * c1.z; acc1.w += w0 * a1.w + w1 * c1.w;
    }
    if (i < e) {
        int s0 = g_srcs[i];
        float w0 = di * g_dinv[s0];
        const float4* p0 = (const float4*)(g_xw1 + (size_t)s0 * DD);
        float4 a0 = p0[lane], a1 = p0[lane + 32];
        acc0.x += w0 * a0.x; acc0.y += w0 * a0.y; acc0.z += w0 * a0.z; acc0.w += w0 * a0.w;
        acc1.x += w0 * a1.x; acc1.y += w0 * a1.y; acc1.z += w0 * a1.z; acc1.w += w0 * a1.w;
    }
    const float4* bb = (const float4*)b1;
    float4 b0 = bb[lane], b1v = bb[lane + 32];
    float o[8];
    o[0] = fmaxf(acc0.x + b0.x, 0.f);  o[1] = fmaxf(acc0.y + b0.y, 0.f);
    o[2] = fmaxf(acc0.z + b0.z, 0.f);  o[3] = fmaxf(acc0.w + b0.w, 0.f);
    o[4] = fmaxf(acc1.x + b1v.x, 0.f); o[5] = fmaxf(acc1.y + b1v.y, 0.f);
    o[6] = fmaxf(acc1.z + b1v.z, 0.f); o[7] = fmaxf(acc1.w + b1v.w, 0.f);
    uint2 h0, l0, h1, l1;
    split2(o[0], o[1], h0.x, l0.x); split2(o[2], o[3], h0.y, l0.y);
    split2(o[4], o[5], h1.x, l1.x); split2(o[6], o[7], h1.y, l1.y);
    size_t base = (size_t)warp * 128;
    *(uint2*)&g_x1hi[base + 2 * lane] = h0;
    *(uint2*)&g_x1lo[base + 2 * lane] = l0;
    *(uint2*)&g_x1hi[base + 64 + 2 * lane] = h1;
    *(uint2*)&g_x1lo[base + 64 + 2 * lane] = l1;
}

// ---------------- GAT aggregation: warp per node ---------------------------
__global__ void gat_agg(const float* __restrict__ b2, float* __restrict__ out, int n) {
    int warp = (blockIdx.x * blockDim.x + threadIdx.x) >> 5;
    if (warp >= n) return;
    int lane = threadIdx.x & 31;
    int s = g_rowptr[warp], e = g_rowptr[warp + 1];
    float ad_n = g_ad[warp];

    // pass 1: per-lane online softmax stats
    float m = -INFINITY, sum = 0.f;
    for (int i = s + lane; i < e; i += 32) {
        int src = g_srcs[i];
        float ev = g_as[src] + ad_n;
        ev = (ev >= 0.f) ? ev : 0.2f * ev;
        if (ev > m) {
            sum = sum * expf(m - ev) + 1.0f;
            m = ev;
        } else {
            sum += expf(ev - m);
        }
    }
#pragma unroll
    for (int off = 16; off > 0; off >>= 1) {
        float mo = __shfl_xor_sync(0xffffffffu, m, off);
        float so = __shfl_xor_sync(0xffffffffu, sum, off);
        float mn = fmaxf(m, mo);
        float sa = (m == mn) ? sum : sum * expf(m - mn);
        float sb = (mo == mn) ? so : so * expf(mo - mn);
        sum = sa + sb;
        m = mn;
    }
    float inv = 1.0f / (sum + 1e-16f);

    // pass 2: weighted accumulate, 2-edge unrolled
    float4 acc0 = make_float4(0.f, 0.f, 0.f, 0.f);
    float4 acc1 = make_float4(0.f, 0.f, 0.f, 0.f);
    int i = s;
    for (; i + 2 <= e; i += 2) {
        int s0 = g_srcs[i], s1 = g_srcs[i + 1];
        float e0 = g_as[s0] + ad_n;
        float e1 = g_as[s1] + ad_n;
        e0 = (e0 >= 0.f) ? e0 : 0.2f * e0;
        e1 = (e1 >= 0.f) ? e1 : 0.2f * e1;
        float w0 = expf(e0 - m) * inv;
        float w1 = expf(e1 - m) * inv;
        const float4* p0 = (const float4*)(g_xw2 + (size_t)s0 * DD);
        const float4* p1 = (const float4*)(g_xw2 + (size_t)s1 * DD);
        float4 a0 = p0[lane], a1 = p0[lane + 32];
        float4 c0 = p1[lane], c1 = p1[lane + 32];
        acc0.x += w0 * a0.x + w1 * c0.x; acc0.y += w0 * a0.y + w1 * c0.y;
        acc0.z += w0 * a0.z + w1 * c0.z; acc0.w += w0 * a0.w + w1 * c0.w;
        acc1.x += w0 * a1.x + w1 * c1.x; acc1.y += w0 * a1.y + w1 * c1.y;
        acc1.z += w0 * a1.z + w1 * c1.z; acc1.w += w0 * a1.w + w1 * c1.w;
    }
    if (i < e) {
        int s0 = g_srcs[i];
        float e0 = g_as[s0] + ad_n;
        e0 = (e0 >= 0.f) ? e0 : 0.2f * e0;
        float w0 = expf(e0 - m) * inv;
        const float4* p0 = (const float4*)(g_xw2 + (size_t)s0 * DD);
        float4 a0 = p0[lane], a1 = p0[lane + 32];
        acc0.x += w0 * a0.x; acc0.y += w0 * a0.y; acc0.z += w0 * a0.z; acc0.w += w0 * a0.w;
        acc1.x += w0 * a1.x; acc1.y += w0 * a1.y; acc1.z += w0 * a1.z; acc1.w += w0 * a1.w;
    }
    const float4* bb = (const float4*)b2;
    float4 b0 = bb[lane], b1v = bb[lane + 32];
    float4 o0 = make_float4(fmaxf(acc0.x + b0.x, 0.f), fmaxf(acc0.y + b0.y, 0.f),
                            fmaxf(acc0.z + b0.z, 0.f), fmaxf(acc0.w + b0.w, 0.f));
    float4 o1 = make_float4(fmaxf(acc1.x + b1v.x, 0.f), fmaxf(acc1.y + b1v.y, 0.f),
                            fmaxf(acc1.z + b1v.z, 0.f), fmaxf(acc1.w + b1v.w, 0.f));
    float4* op = (float4*)(out + (size_t)warp * DD);
    op[lane] = o0;
    op[lane + 32] = o1;
}

// ---------------- launch ----------------------------------------------------
static cudaStream_t s_side = nullptr;
static cudaEvent_t ev_fork = nullptr, ev_join = nullptr;

extern "C" void kernel_launch(void* const* d_in, const int* in_sizes, int n_in,
                              void* d_out, int out_size) {
    const float* x       = (const float*)d_in[0];
    const int*   ei      = (const int*)  d_in[1];
    const float* W1      = (const float*)d_in[2];
    const float* b1      = (const float*)d_in[3];
    const float* W2      = (const float*)d_in[4];
    const float* att_src = (const float*)d_in[5];
    const float* att_dst = (const float*)d_in[6];
    const float* b2      = (const float*)d_in[7];
    float* out = (float*)d_out;

    int n = in_sizes[0] / DD;
    int E = in_sizes[1] / 2;
    if (n > N_MAX) n = N_MAX;
    if (E > E_MAX) E = E_MAX;
    const int* src = ei;
    const int* dst = ei + E;
    int nb = (n + 255) / 256;

    if (!s_side) {   // first call is the (non-capture) correctness run
        cudaStreamCreateWithFlags(&s_side, cudaStreamNonBlocking);
        cudaEventCreateWithFlags(&ev_fork, cudaEventDisableTiming);
        cudaEventCreateWithFlags(&ev_join, cudaEventDisableTiming);
    }

    dim3 ggrid((n + 127) / 128, 4);   // 128x64 tiles over [M,256]

    // fork: CSR build on side stream; splits + GEMM1 on main stream
    cudaEventRecord(ev_fork, 0);
    cudaStreamWaitEvent(s_side, ev_fork, 0);

    k_init_cnt<<<(n + 255) / 256, 256, 0, s_side>>>(n);
    k_count<<<(E + 255) / 256, 256, 0, s_side>>>(dst, E);
    k_scan1<<<nb, 256, 0, s_side>>>(n);
    k_scan2<<<1, 32, 0, s_side>>>(nb, n);
    k_scan3_self<<<(n + 255) / 256, 256, 0, s_side>>>(n);
    k_scatter<<<(E + 255) / 256, 256, 0, s_side>>>(src, dst, E);
    cudaEventRecord(ev_join, s_side);

    k_split_w<<<(65536 + 255) / 256, 256>>>(W1, W2);
    k_split_x<<<(n * 64 + 255) / 256, 256>>>(x, n);
    sgemm_pk<<<ggrid, 256>>>(n, nullptr, nullptr, 0);       // xw1 = x @ W1

    cudaStreamWaitEvent(0, ev_join, 0);                     // CSR ready

    gcn_agg<<<(n + 7) / 8, 256>>>(b1, n);                   // x1 (packed bf16)
    sgemm_pk<<<ggrid, 256>>>(n, att_src, att_dst, 1);       // xw2 + fused dots
    gat_agg<<<(n + 7) / 8, 256>>>(b2, out, n);              // out = relu(GAT)
}

// round 10
// speedup vs baseline: 1.5407x; 1.0165x over previous
#include <cuda_runtime.h>
#include <cuda_bf16.h>
#include <math.h>
#include <stdint.h>

#define DD 256
#define N_MAX 10000
#define NPAD 10112            // 79 * 128, covers last GEMM tile rows
#define E_MAX 320000
#define ET_MAX (E_MAX + N_MAX)
#define NB_MAX 64

// ---------------- scratch (device globals; no allocation allowed) ----------
__device__ float g_xw1[N_MAX * DD];        // x @ W1 (fp32, read by gcn_agg)
__device__ float g_xw2[N_MAX * DD];        // x1 @ W2 (fp32, read by gat_agg)
__device__ uint32_t g_Ahi[NPAD * 128];     // x split, packed bf16x2 [row][kpair]
__device__ uint32_t g_Alo[NPAD * 128];
__device__ uint32_t g_x1hi[NPAD * 128];    // relu(GCN) split, packed
__device__ uint32_t g_x1lo[NPAD * 128];
__device__ uint32_t g_B1hi[256 * 128];     // W1 split, packed [col][kpair]
__device__ uint32_t g_B1lo[256 * 128];
__device__ uint32_t g_B2hi[256 * 128];     // W2 split
__device__ uint32_t g_B2lo[256 * 128];
__device__ float g_as[N_MAX];              // xw2 . att_src  (per node)
__device__ float g_ad[N_MAX];              // xw2 . att_dst
__device__ float g_dinv[N_MAX];
__device__ int   g_cnt[N_MAX];             // zero-init at load; re-zeroed each run
__device__ int   g_rowptr[N_MAX + 1];
__device__ int   g_wp[N_MAX];
__device__ int   g_srcs[ET_MAX];
__device__ int   g_bsum[NB_MAX];
__device__ int   g_boff[NB_MAX];

// split two fp32 into packed bf16x2 hi and lo (element0 in low half)
__device__ __forceinline__ void split2(float x0, float x1, uint32_t& hi, uint32_t& lo) {
    __nv_bfloat162 h = __floats2bfloat162_rn(x0, x1);
    float2 hf = __bfloat1622float2(h);
    __nv_bfloat162 l = __floats2bfloat162_rn(x0 - hf.x, x1 - hf.y);
    hi = *(uint32_t*)&h;
    lo = *(uint32_t*)&l;
}

// ---------------- CSR build -------------------------------------------------
__global__ void k_count(const int* __restrict__ dst, int E) {
    int e = blockIdx.x * blockDim.x + threadIdx.x;
    if (e < E) atomicAdd(&g_cnt[dst[e]], 1);
}

// scan1: deg = cnt + 1 (self loop), local prefix + block sums + dinv
__global__ void k_scan1(int n) {
    int i = blockIdx.x * 256 + threadIdx.x;
    int c = (i < n) ? g_cnt[i] + 1 : 0;
    if (i < n) g_dinv[i] = rsqrtf((float)c);
    int lane = threadIdx.x & 31, w = threadIdx.x >> 5;
    int v = c;
#pragma unroll
    for (int o = 1; o < 32; o <<= 1) {
        int t = __shfl_up_sync(0xffffffffu, v, o);
        if (lane >= o) v += t;
    }
    __shared__ int ws[8];
    if (lane == 31) ws[w] = v;
    __syncthreads();
    if (w == 0 && lane < 8) {
        int s = ws[lane];
#pragma unroll
        for (int o = 1; o < 8; o <<= 1) {
            int t = __shfl_up_sync(0xffu, s, o);
            if (lane >= o) s += t;
        }
        ws[lane] = s;
    }
    __syncthreads();
    int excl = v - c + (w ? ws[w - 1] : 0);
    if (i < n) g_rowptr[i] = excl;
    if (threadIdx.x == 0) g_bsum[blockIdx.x] = ws[7];
}

__global__ void k_scan2(int nb, int n) {
    int lane = threadIdx.x;
    int v0 = (lane < nb) ? g_bsum[lane] : 0;
    int v1 = (lane + 32 < nb) ? g_bsum[lane + 32] : 0;
    int s0 = v0, s1 = v1;
#pragma unroll
    for (int o = 1; o < 32; o <<= 1) {
        int t = __shfl_up_sync(0xffffffffu, s0, o);
        if (lane >= o) s0 += t;
        int t1 = __shfl_up_sync(0xffffffffu, s1, o);
        if (lane >= o) s1 += t1;
    }
    int tot0 = __shfl_sync(0xffffffffu, s0, 31);
    s1 += tot0;
    g_boff[lane] = s0 - v0;
    g_boff[lane + 32] = s1 - v1;
    if (lane == 31) g_rowptr[n] = s1;
}

// stage 3: apply offsets + self-loop + cursors + zero att dots + re-zero cnt
__global__ void k_scan3_self(int n) {
    int i = blockIdx.x * blockDim.x + threadIdx.x;
    if (i < n) {
        int p = g_rowptr[i] + g_boff[i >> 8];
        g_rowptr[i] = p;
        g_srcs[p] = i;
        g_wp[i] = p + 1;
        g_as[i] = 0.0f;      // fused-dot accumulators for layer 2
        g_ad[i] = 0.0f;
        g_cnt[i] = 0;        // ready for next run (after scan1 consumed it)
    }
}

__global__ void k_scatter(const int* __restrict__ src, const int* __restrict__ dst, int E) {
    int e = blockIdx.x * blockDim.x + threadIdx.x;
    if (e < E) {
        int d = dst[e];
        int pos = atomicAdd(&g_wp[d], 1);
        g_srcs[pos] = src[e];
    }
}

// ---------------- merged pre-split kernel -----------------------------------
// t < 65536:        W1/W2 [256,256] row-major(k,n) -> packed [n][kpair]
// t >= 65536:       x [n,256] fp32 -> g_Ahi/g_Alo packed [row][kpair]
__global__ void k_split(const float* __restrict__ x, const float* __restrict__ W1,
                        const float* __restrict__ W2, int n) {
    int t = blockIdx.x * blockDim.x + threadIdx.x;
    if (t < 65536) {
        int sel = t >> 15;
        int u = t & 32767;
        int kp = u >> 8, nn = u & 255;
        const float* W = sel ? W2 : W1;
        uint32_t* oh = sel ? g_B2hi : g_B1hi;
        uint32_t* ol = sel ? g_B2lo : g_B1lo;
        float w0 = W[(2 * kp) * 256 + nn];
        float w1 = W[(2 * kp + 1) * 256 + nn];
        uint32_t h, l;
        split2(w0, w1, h, l);
        oh[nn * 128 + kp] = h;
        ol[nn * 128 + kp] = l;
    } else {
        int i = t - 65536;
        if (i < n * 64) {
            float4 v = ((const float4*)x)[i];
            uint2 h, l;
            split2(v.x, v.y, h.x, l.x);
            split2(v.z, v.w, h.y, l.y);
            *(uint2*)&g_Ahi[(size_t)i * 2] = h;
            *(uint2*)&g_Alo[(size_t)i * 2] = l;
        }
    }
}

// ---------------- bf16x3 tensor GEMM on pre-split operands -----------------
// block tile 128x64, 8 warps (2m x 4n), mma m16n8k16 bf16, fp32 accum.
// Fragments loaded with ldmatrix (x4 for A, x2 for B). layer selects
// operands INSIDE the kernel (device globals can't cross the launch ABI).

__device__ __forceinline__ void mma_bf16(float* c, const uint32_t* a, const uint32_t* b) {
    asm volatile(
        "mma.sync.aligned.m16n8k16.row.col.f32.bf16.bf16.f32 "
        "{%0,%1,%2,%3},{%4,%5,%6,%7},{%8,%9},{%0,%1,%2,%3};"
        : "+f"(c[0]), "+f"(c[1]), "+f"(c[2]), "+f"(c[3])
        : "r"(a[0]), "r"(a[1]), "r"(a[2]), "r"(a[3]), "r"(b[0]), "r"(b[1]));
}

__device__ __forceinline__ void ldsm_x4(uint32_t* r, uint32_t saddr) {
    asm volatile("ldmatrix.sync.aligned.m8n8.x4.shared.b16 {%0,%1,%2,%3}, [%4];"
        : "=r"(r[0]), "=r"(r[1]), "=r"(r[2]), "=r"(r[3]) : "r"(saddr));
}
__device__ __forceinline__ void ldsm_x2(uint32_t* r, uint32_t saddr) {
    asm volatile("ldmatrix.sync.aligned.m8n8.x2.shared.b16 {%0,%1}, [%2];"
        : "=r"(r[0]), "=r"(r[1]) : "r"(saddr));
}

#define KC 32
#define LDA 20   // u32 stride; row pitch 80B -> ldmatrix conflict-free, 16B aligned
#define LDB 20

__global__ void __launch_bounds__(256, 2)
sgemm_pk(int M, const float* __restrict__ asrc, const float* __restrict__ adst, int layer) {
    const uint32_t* __restrict__ Ahi = layer ? g_x1hi : g_Ahi;
    const uint32_t* __restrict__ Alo = layer ? g_x1lo : g_Alo;
    const uint32_t* __restrict__ Bhi = layer ? g_B2hi : g_B1hi;
    const uint32_t* __restrict__ Blo = layer ? g_B2lo : g_B1lo;
    float* __restrict__ C = layer ? g_xw2 : g_xw1;

    __shared__ uint32_t As_hi[128][LDA];
    __shared__ uint32_t As_lo[128][LDA];
    __shared__ uint32_t Bs_hi[64][LDB];
    __shared__ uint32_t Bs_lo[64][LDB];

    int tid = threadIdx.x;
    int w = tid >> 5, lane = tid & 31;
    int wm = (w & 1) * 64;
    int wn = (w >> 1) * 16;
    int g = lane >> 2, tig = lane & 3;
    int blockRow = blockIdx.x * 128, blockCol = blockIdx.y * 64;

    // ldmatrix per-lane address components
    int a_r  = ((lane >> 3) & 1) * 8 + (lane & 7);   // row within 16-row tile
    int a_kc = (lane >> 4) * 4;                      // kpair sub-offset 0/4
    int b_r  = lane & 7;                             // n-row within 8
    int b_kc = ((lane >> 3) & 1) * 4;                // kpair sub-offset 0/4
    uint32_t sa_hi = (uint32_t)__cvta_generic_to_shared(As_hi);
    uint32_t sa_lo = (uint32_t)__cvta_generic_to_shared(As_lo);
    uint32_t sb_hi = (uint32_t)__cvta_generic_to_shared(Bs_hi);
    uint32_t sb_lo = (uint32_t)__cvta_generic_to_shared(Bs_lo);

    float acc[4][2][4];
#pragma unroll
    for (int mt = 0; mt < 4; mt++)
#pragma unroll
        for (int nt = 0; nt < 2; nt++)
#pragma unroll
            for (int q = 0; q < 4; q++) acc[mt][nt][q] = 0.0f;

    int arow = tid >> 1;            // 0..127
    int ahalf = (tid & 1) * 8;      // kpair half
    int bcol = tid >> 2;            // 0..63
    int bq = (tid & 3) * 4;         // kpair quarter

    const uint32_t* pa_h = Ahi + (size_t)(blockRow + arow) * 128 + ahalf;
    const uint32_t* pa_l = Alo + (size_t)(blockRow + arow) * 128 + ahalf;
    const uint32_t* pb_h = Bhi + (size_t)(blockCol + bcol) * 128 + bq;
    const uint32_t* pb_l = Blo + (size_t)(blockCol + bcol) * 128 + bq;

    for (int k0 = 0; k0 < DD; k0 += KC) {
        int kp0 = k0 >> 1;
        uint4 ah0 = *(const uint4*)(pa_h + kp0);
        uint4 ah1 = *(const uint4*)(pa_h + kp0 + 4);
        uint4 al0 = *(const uint4*)(pa_l + kp0);
        uint4 al1 = *(const uint4*)(pa_l + kp0 + 4);
        uint4 bhv = *(const uint4*)(pb_h + kp0);
        uint4 blv = *(const uint4*)(pb_l + kp0);
        *(uint4*)&As_hi[arow][ahalf] = ah0;
        *(uint4*)&As_hi[arow][ahalf + 4] = ah1;
        *(uint4*)&As_lo[arow][ahalf] = al0;
        *(uint4*)&As_lo[arow][ahalf + 4] = al1;
        *(uint4*)&Bs_hi[bcol][bq] = bhv;
        *(uint4*)&Bs_lo[bcol][bq] = blv;
        __syncthreads();

#pragma unroll
        for (int kk = 0; kk < KC; kk += 16) {
            int kb = kk >> 1;
            uint32_t ah[4][4], al[4][4], bh[2][2], bl[2][2];
#pragma unroll
            for (int mt = 0; mt < 4; mt++) {
                uint32_t off = (uint32_t)((wm + mt * 16 + a_r) * LDA + kb + a_kc) * 4u;
                ldsm_x4(ah[mt], sa_hi + off);
                ldsm_x4(al[mt], sa_lo + off);
            }
#pragma unroll
            for (int nt = 0; nt < 2; nt++) {
                uint32_t off = (uint32_t)((wn + nt * 8 + b_r) * LDB + kb + b_kc) * 4u;
                ldsm_x2(bh[nt], sb_hi + off);
                ldsm_x2(bl[nt], sb_lo + off);
            }
#pragma unroll
            for (int mt = 0; mt < 4; mt++)
#pragma unroll
                for (int nt = 0; nt < 2; nt++) {
                    mma_bf16(acc[mt][nt], al[mt], bh[nt]);   // small terms first
                    mma_bf16(acc[mt][nt], ah[mt], bl[nt]);
                    mma_bf16(acc[mt][nt], ah[mt], bh[nt]);
                }
        }
        __syncthreads();
    }

    // ---- store C ----
#pragma unroll
    for (int mt = 0; mt < 4; mt++) {
        int r0 = blockRow + wm + mt * 16 + g;
        int r1 = r0 + 8;
#pragma unroll
        for (int nt = 0; nt < 2; nt++) {
            int col = blockCol + wn + nt * 8 + 2 * tig;
            if (r0 < M) *(float2*)(C + (size_t)r0 * DD + col) = make_float2(acc[mt][nt][0], acc[mt][nt][1]);
            if (r1 < M) *(float2*)(C + (size_t)r1 * DD + col) = make_float2(acc[mt][nt][2], acc[mt][nt][3]);
        }
    }

    // ---- fused attention dot products (layer 2 only) ----
    if (layer) {
#pragma unroll
        for (int mt = 0; mt < 4; mt++) {
            float s0 = 0.f, d0 = 0.f, s1 = 0.f, d1 = 0.f;
#pragma unroll
            for (int nt = 0; nt < 2; nt++) {
                int col = blockCol + wn + nt * 8 + 2 * tig;
                float a0 = asrc[col], a1 = asrc[col + 1];
                float t0 = adst[col], t1 = adst[col + 1];
                s0 += acc[mt][nt][0] * a0 + acc[mt][nt][1] * a1;
                d0 += acc[mt][nt][0] * t0 + acc[mt][nt][1] * t1;
                s1 += acc[mt][nt][2] * a0 + acc[mt][nt][3] * a1;
                d1 += acc[mt][nt][2] * t0 + acc[mt][nt][3] * t1;
            }
#pragma unroll
            for (int off = 1; off <= 2; off <<= 1) {
                s0 += __shfl_xor_sync(0xffffffffu, s0, off);
                d0 += __shfl_xor_sync(0xffffffffu, d0, off);
                s1 += __shfl_xor_sync(0xffffffffu, s1, off);
                d1 += __shfl_xor_sync(0xffffffffu, d1, off);
            }
            if (tig == 0) {
                int r0 = blockRow + wm + mt * 16 + g;
                int r1 = r0 + 8;
                if (r0 < M) { atomicAdd(&g_as[r0], s0); atomicAdd(&g_ad[r0], d0); }
                if (r1 < M) { atomicAdd(&g_as[r1], s1); atomicAdd(&g_ad[r1], d1); }
            }
        }
    }
}

// ---------------- GCN aggregation: warp per node, emits packed bf16 --------
__global__ void gcn_agg(const float* __restrict__ b1, int n) {
    int warp = (blockIdx.x * blockDim.x + threadIdx.x) >> 5;
    if (warp >= n) return;
    int lane = threadIdx.x & 31;
    float di = g_dinv[warp];
    int s = g_rowptr[warp], e = g_rowptr[warp + 1];
    float4 acc0 = make_float4(0.f, 0.f, 0.f, 0.f);
    float4 acc1 = make_float4(0.f, 0.f, 0.f, 0.f);
    int i = s;
    for (; i + 2 <= e; i += 2) {
        int s0 = g_srcs[i], s1 = g_srcs[i + 1];
        float w0 = di * g_dinv[s0];
        float w1 = di * g_dinv[s1];
        const float4* p0 = (const float4*)(g_xw1 + (size_t)s0 * DD);
        const float4* p1 = (const float4*)(g_xw1 + (size_t)s1 * DD);
        float4 a0 = p0[lane], a1 = p0[lane + 32];
        float4 c0 = p1[lane], c1 = p1[lane + 32];
        acc0.x += w0 * a0.x + w1 * c0.x; acc0.y += w0 * a0.y + w1 * c0.y;
        acc0.z += w0 * a0.z + w1 * c0.z; acc0.w += w0 * a0.w + w1 * c0.w;
        acc1.x += w0 * a1.x + w1 * c1.x; acc1.y += w0 * a1.y + w1 * c1.y;
        acc1.z += w0 * a1.z + w1 * c1.z; acc1.w += w0 * a1.w + w1 * c1.w;
    }
    if (i < e) {
        int s0 = g_srcs[i];
        float w0 = di * g_dinv[s0];
        const float4* p0 = (const float4*)(g_xw1 + (size_t)s0 * DD);
        float4 a0 = p0[lane], a1 = p0[lane + 32];
        acc0.x += w0 * a0.x; acc0.y += w0 * a0.y; acc0.z += w0 * a0.z; acc0.w += w0 * a0.w;
        acc1.x += w0 * a1.x; acc1.y += w0 * a1.y; acc1.z += w0 * a1.z; acc1.w += w0 * a1.w;
    }
    const float4* bb = (const float4*)b1;
    float4 b0 = bb[lane], b1v = bb[lane + 32];
    float o[8];
    o[0] = fmaxf(acc0.x + b0.x, 0.f);  o[1] = fmaxf(acc0.y + b0.y, 0.f);
    o[2] = fmaxf(acc0.z + b0.z, 0.f);  o[3] = fmaxf(acc0.w + b0.w, 0.f);
    o[4] = fmaxf(acc1.x + b1v.x, 0.f); o[5] = fmaxf(acc1.y + b1v.y, 0.f);
    o[6] = fmaxf(acc1.z + b1v.z, 0.f); o[7] = fmaxf(acc1.w + b1v.w, 0.f);
    uint2 h0, l0, h1, l1;
    split2(o[0], o[1], h0.x, l0.x); split2(o[2], o[3], h0.y, l0.y);
    split2(o[4], o[5], h1.x, l1.x); split2(o[6], o[7], h1.y, l1.y);
    size_t base = (size_t)warp * 128;
    *(uint2*)&g_x1hi[base + 2 * lane] = h0;
    *(uint2*)&g_x1lo[base + 2 * lane] = l0;
    *(uint2*)&g_x1hi[base + 64 + 2 * lane] = h1;
    *(uint2*)&g_x1lo[base + 64 + 2 * lane] = l1;
}

// ---------------- GAT aggregation: warp per node ---------------------------
__global__ void gat_agg(const float* __restrict__ b2, float* __restrict__ out, int n) {
    int warp = (blockIdx.x * blockDim.x + threadIdx.x) >> 5;
    if (warp >= n) return;
    int lane = threadIdx.x & 31;
    int s = g_rowptr[warp], e = g_rowptr[warp + 1];
    float ad_n = g_ad[warp];

    // pass 1: per-lane online softmax stats
    float m = -INFINITY, sum = 0.f;
    for (int i = s + lane; i < e; i += 32) {
        int src = g_srcs[i];
        float ev = g_as[src] + ad_n;
        ev = (ev >= 0.f) ? ev : 0.2f * ev;
        if (ev > m) {
            sum = sum * expf(m - ev) + 1.0f;
            m = ev;
        } else {
            sum += expf(ev - m);
        }
    }
#pragma unroll
    for (int off = 16; off > 0; off >>= 1) {
        float mo = __shfl_xor_sync(0xffffffffu, m, off);
        float so = __shfl_xor_sync(0xffffffffu, sum, off);
        float mn = fmaxf(m, mo);
        float sa = (m == mn) ? sum : sum * expf(m - mn);
        float sb = (mo == mn) ? so : so * expf(mo - mn);
        sum = sa + sb;
        m = mn;
    }
    float inv = 1.0f / (sum + 1e-16f);

    // pass 2: weighted accumulate, 2-edge unrolled
    float4 acc0 = make_float4(0.f, 0.f, 0.f, 0.f);
    float4 acc1 = make_float4(0.f, 0.f, 0.f, 0.f);
    int i = s;
    for (; i + 2 <= e; i += 2) {
        int s0 = g_srcs[i], s1 = g_srcs[i + 1];
        float e0 = g_as[s0] + ad_n;
        float e1 = g_as[s1] + ad_n;
        e0 = (e0 >= 0.f) ? e0 : 0.2f * e0;
        e1 = (e1 >= 0.f) ? e1 : 0.2f * e1;
        float w0 = expf(e0 - m) * inv;
        float w1 = expf(e1 - m) * inv;
        const float4* p0 = (const float4*)(g_xw2 + (size_t)s0 * DD);
        const float4* p1 = (const float4*)(g_xw2 + (size_t)s1 * DD);
        float4 a0 = p0[lane], a1 = p0[lane + 32];
        float4 c0 = p1[lane], c1 = p1[lane + 32];
        acc0.x += w0 * a0.x + w1 * c0.x; acc0.y += w0 * a0.y + w1 * c0.y;
        acc0.z += w0 * a0.z + w1 * c0.z; acc0.w += w0 * a0.w + w1 * c0.w;
        acc1.x += w0 * a1.x + w1 * c1.x; acc1.y += w0 * a1.y + w1 * c1.y;
        acc1.z += w0 * a1.z + w1 * c1.z; acc1.w += w0 * a1.w + w1 * c1.w;
    }
    if (i < e) {
        int s0 = g_srcs[i];
        float e0 = g_as[s0] + ad_n;
        e0 = (e0 >= 0.f) ? e0 : 0.2f * e0;
        float w0 = expf(e0 - m) * inv;
        const float4* p0 = (const float4*)(g_xw2 + (size_t)s0 * DD);
        float4 a0 = p0[lane], a1 = p0[lane + 32];
        acc0.x += w0 * a0.x; acc0.y += w0 * a0.y; acc0.z += w0 * a0.z; acc0.w += w0 * a0.w;
        acc1.x += w0 * a1.x; acc1.y += w0 * a1.y; acc1.z += w0 * a1.z; acc1.w += w0 * a1.w;
    }
    const float4* bb = (const float4*)b2;
    float4 b0 = bb[lane], b1v = bb[lane + 32];
    float4 o0 = make_float4(fmaxf(acc0.x + b0.x, 0.f), fmaxf(acc0.y + b0.y, 0.f),
                            fmaxf(acc0.z + b0.z, 0.f), fmaxf(acc0.w + b0.w, 0.f));
    float4 o1 = make_float4(fmaxf(acc1.x + b1v.x, 0.f), fmaxf(acc1.y + b1v.y, 0.f),
                            fmaxf(acc1.z + b1v.z, 0.f), fmaxf(acc1.w + b1v.w, 0.f));
    float4* op = (float4*)(out + (size_t)warp * DD);
    op[lane] = o0;
    op[lane + 32] = o1;
}

// ---------------- launch ----------------------------------------------------
static cudaStream_t s_side = nullptr;
static cudaEvent_t ev_fork = nullptr, ev_join = nullptr;

extern "C" void kernel_launch(void* const* d_in, const int* in_sizes, int n_in,
                              void* d_out, int out_size) {
    const float* x       = (const float*)d_in[0];
    const int*   ei      = (const int*)  d_in[1];
    const float* W1      = (const float*)d_in[2];
    const float* b1      = (const float*)d_in[3];
    const float* W2      = (const float*)d_in[4];
    const float* att_src = (const float*)d_in[5];
    const float* att_dst = (const float*)d_in[6];
    const float* b2      = (const float*)d_in[7];
    float* out = (float*)d_out;

    int n = in_sizes[0] / DD;
    int E = in_sizes[1] / 2;
    if (n > N_MAX) n = N_MAX;
    if (E > E_MAX) E = E_MAX;
    const int* src = ei;
    const int* dst = ei + E;
    int nb = (n + 255) / 256;

    if (!s_side) {   // first call is the (non-capture) correctness run
        cudaStreamCreateWithFlags(&s_side, cudaStreamNonBlocking);
        cudaEventCreateWithFlags(&ev_fork, cudaEventDisableTiming);
        cudaEventCreateWithFlags(&ev_join, cudaEventDisableTiming);
    }

    dim3 ggrid((n + 127) / 128, 4);   // 128x64 tiles over [M,256]
    int splitThreads = 65536 + n * 64;

    // fork: CSR build on side stream; split + GEMM1 on main stream.
    // Enqueue order puts sgemm_pk at capture-launch index 3 (ncu samples #3).
    cudaEventRecord(ev_fork, 0);
    cudaStreamWaitEvent(s_side, ev_fork, 0);

    k_count<<<(E + 255) / 256, 256, 0, s_side>>>(dst, E);          // 0
    k_scan1<<<nb, 256, 0, s_side>>>(n);                            // 1
    k_split<<<(splitThreads + 255) / 256, 256>>>(x, W1, W2, n);    // 2 (main)
    sgemm_pk<<<ggrid, 256>>>(n, nullptr, nullptr, 0);              // 3 (main, profiled)
    k_scan2<<<1, 32, 0, s_side>>>(nb, n);                          // 4
    k_scan3_self<<<(n + 255) / 256, 256, 0, s_side>>>(n);          // 5
    k_scatter<<<(E + 255) / 256, 256, 0, s_side>>>(src, dst, E);   // 6
    cudaEventRecord(ev_join, s_side);

    cudaStreamWaitEvent(0, ev_join, 0);                            // CSR ready

    gcn_agg<<<(n + 7) / 8, 256>>>(b1, n);                          // 7
    sgemm_pk<<<ggrid, 256>>>(n, att_src, att_dst, 1);              // 8
    gat_agg<<<(n + 7) / 8, 256>>>(b2, out, n);                     // 9
}

// round 11
// speedup vs baseline: 1.6514x; 1.0718x over previous
#include <cuda_runtime.h>
#include <cuda_bf16.h>
#include <math.h>
#include <stdint.h>

#define DD 256
#define N_MAX 10000
#define NPAD 10112            // 158 * 64, covers last GEMM tile rows
#define E_MAX 320000
#define ET_MAX (E_MAX + N_MAX)
#define NB_MAX 64

// ---------------- scratch (device globals; no allocation allowed) ----------
__device__ float g_xw1[N_MAX * DD];        // x @ W1 (fp32, read by gcn_agg)
__device__ float g_xw2[N_MAX * DD];        // x1 @ W2 (fp32, read by gat_agg)
__device__ uint32_t g_Ahi[NPAD * 128];     // x split, packed bf16x2 [row][kpair]
__device__ uint32_t g_Alo[NPAD * 128];
__device__ uint32_t g_x1hi[NPAD * 128];    // relu(GCN) split, packed
__device__ uint32_t g_x1lo[NPAD * 128];
__device__ uint32_t g_B1hi[256 * 128];     // W1 split, packed [col][kpair]
__device__ uint32_t g_B1lo[256 * 128];
__device__ uint32_t g_B2hi[256 * 128];     // W2 split
__device__ uint32_t g_B2lo[256 * 128];
__device__ float g_as[N_MAX];              // xw2 . att_src  (per node)
__device__ float g_ad[N_MAX];              // xw2 . att_dst
__device__ float g_dinv[N_MAX];
__device__ int   g_cnt[N_MAX];             // zero-init at load; re-zeroed each run
__device__ int   g_rowptr[N_MAX + 1];
__device__ int   g_wp[N_MAX];
__device__ int   g_srcs[ET_MAX];
__device__ int   g_bsum[NB_MAX];
__device__ int   g_boff[NB_MAX];

// split two fp32 into packed bf16x2 hi and lo (element0 in low half)
__device__ __forceinline__ void split2(float x0, float x1, uint32_t& hi, uint32_t& lo) {
    __nv_bfloat162 h = __floats2bfloat162_rn(x0, x1);
    float2 hf = __bfloat1622float2(h);
    __nv_bfloat162 l = __floats2bfloat162_rn(x0 - hf.x, x1 - hf.y);
    hi = *(uint32_t*)&h;
    lo = *(uint32_t*)&l;
}

// ---------------- CSR build -------------------------------------------------
__global__ void k_count(const int* __restrict__ dst, int E) {
    int e = blockIdx.x * blockDim.x + threadIdx.x;
    if (e < E) atomicAdd(&g_cnt[dst[e]], 1);
}

// scan1: deg = cnt + 1 (self loop), local prefix + block sums + dinv
__global__ void k_scan1(int n) {
    int i = blockIdx.x * 256 + threadIdx.x;
    int c = (i < n) ? g_cnt[i] + 1 : 0;
    if (i < n) g_dinv[i] = rsqrtf((float)c);
    int lane = threadIdx.x & 31, w = threadIdx.x >> 5;
    int v = c;
#pragma unroll
    for (int o = 1; o < 32; o <<= 1) {
        int t = __shfl_up_sync(0xffffffffu, v, o);
        if (lane >= o) v += t;
    }
    __shared__ int ws[8];
    if (lane == 31) ws[w] = v;
    __syncthreads();
    if (w == 0 && lane < 8) {
        int s = ws[lane];
#pragma unroll
        for (int o = 1; o < 8; o <<= 1) {
            int t = __shfl_up_sync(0xffu, s, o);
            if (lane >= o) s += t;
        }
        ws[lane] = s;
    }
    __syncthreads();
    int excl = v - c + (w ? ws[w - 1] : 0);
    if (i < n) g_rowptr[i] = excl;
    if (threadIdx.x == 0) g_bsum[blockIdx.x] = ws[7];
}

__global__ void k_scan2(int nb, int n) {
    int lane = threadIdx.x;
    int v0 = (lane < nb) ? g_bsum[lane] : 0;
    int v1 = (lane + 32 < nb) ? g_bsum[lane + 32] : 0;
    int s0 = v0, s1 = v1;
#pragma unroll
    for (int o = 1; o < 32; o <<= 1) {
        int t = __shfl_up_sync(0xffffffffu, s0, o);
        if (lane >= o) s0 += t;
        int t1 = __shfl_up_sync(0xffffffffu, s1, o);
        if (lane >= o) s1 += t1;
    }
    int tot0 = __shfl_sync(0xffffffffu, s0, 31);
    s1 += tot0;
    g_boff[lane] = s0 - v0;
    g_boff[lane + 32] = s1 - v1;
    if (lane == 31) g_rowptr[n] = s1;
}

// stage 3: apply offsets + self-loop + cursors + zero att dots + re-zero cnt
__global__ void k_scan3_self(int n) {
    int i = blockIdx.x * blockDim.x + threadIdx.x;
    if (i < n) {
        int p = g_rowptr[i] + g_boff[i >> 8];
        g_rowptr[i] = p;
        g_srcs[p] = i;
        g_wp[i] = p + 1;
        g_as[i] = 0.0f;      // fused-dot accumulators for layer 2
        g_ad[i] = 0.0f;
        g_cnt[i] = 0;        // ready for next run (after scan1 consumed it)
    }
}

__global__ void k_scatter(const int* __restrict__ src, const int* __restrict__ dst, int E) {
    int e = blockIdx.x * blockDim.x + threadIdx.x;
    if (e < E) {
        int d = dst[e];
        int pos = atomicAdd(&g_wp[d], 1);
        g_srcs[pos] = src[e];
    }
}

// ---------------- merged pre-split kernel -----------------------------------
__global__ void k_split(const float* __restrict__ x, const float* __restrict__ W1,
                        const float* __restrict__ W2, int n) {
    int t = blockIdx.x * blockDim.x + threadIdx.x;
    if (t < 65536) {
        int sel = t >> 15;
        int u = t & 32767;
        int kp = u >> 8, nn = u & 255;
        const float* W = sel ? W2 : W1;
        uint32_t* oh = sel ? g_B2hi : g_B1hi;
        uint32_t* ol = sel ? g_B2lo : g_B1lo;
        float w0 = W[(2 * kp) * 256 + nn];
        float w1 = W[(2 * kp + 1) * 256 + nn];
        uint32_t h, l;
        split2(w0, w1, h, l);
        oh[nn * 128 + kp] = h;
        ol[nn * 128 + kp] = l;
    } else {
        int i = t - 65536;
        if (i < n * 64) {
            float4 v = ((const float4*)x)[i];
            uint2 h, l;
            split2(v.x, v.y, h.x, l.x);
            split2(v.z, v.w, h.y, l.y);
            *(uint2*)&g_Ahi[(size_t)i * 2] = h;
            *(uint2*)&g_Alo[(size_t)i * 2] = l;
        }
    }
}

// ---------------- bf16x3 tensor GEMM on pre-split operands -----------------
// block tile 64x64, 4 warps (2m x 2n), warp tile 32x32, mma m16n8k16 bf16.
// High-occupancy config: ~20 warps/SM, grid fits in ONE wave.
// D += Al*Bh + Ah*Bl + Ah*Bh, fp32 accumulate.

__device__ __forceinline__ void mma_bf16(float* c, const uint32_t* a, const uint32_t* b) {
    asm volatile(
        "mma.sync.aligned.m16n8k16.row.col.f32.bf16.bf16.f32 "
        "{%0,%1,%2,%3},{%4,%5,%6,%7},{%8,%9},{%0,%1,%2,%3};"
        : "+f"(c[0]), "+f"(c[1]), "+f"(c[2]), "+f"(c[3])
        : "r"(a[0]), "r"(a[1]), "r"(a[2]), "r"(a[3]), "r"(b[0]), "r"(b[1]));
}

__device__ __forceinline__ void ldsm_x4(uint32_t* r, uint32_t saddr) {
    asm volatile("ldmatrix.sync.aligned.m8n8.x4.shared.b16 {%0,%1,%2,%3}, [%4];"
        : "=r"(r[0]), "=r"(r[1]), "=r"(r[2]), "=r"(r[3]) : "r"(saddr));
}
__device__ __forceinline__ void ldsm_x2(uint32_t* r, uint32_t saddr) {
    asm volatile("ldmatrix.sync.aligned.m8n8.x2.shared.b16 {%0,%1}, [%2];"
        : "=r"(r[0]), "=r"(r[1]) : "r"(saddr));
}

#define KC 32
#define LDA 20   // u32 stride; row pitch 80B -> ldmatrix conflict-free, 16B aligned
#define LDB 20
#define TM 64    // block tile rows

__global__ void __launch_bounds__(128, 5)
sgemm_pk(int M, const float* __restrict__ asrc, const float* __restrict__ adst, int layer) {
    const uint32_t* __restrict__ Ahi = layer ? g_x1hi : g_Ahi;
    const uint32_t* __restrict__ Alo = layer ? g_x1lo : g_Alo;
    const uint32_t* __restrict__ Bhi = layer ? g_B2hi : g_B1hi;
    const uint32_t* __restrict__ Blo = layer ? g_B2lo : g_B1lo;
    float* __restrict__ C = layer ? g_xw2 : g_xw1;

    __shared__ uint32_t As_hi[TM][LDA];
    __shared__ uint32_t As_lo[TM][LDA];
    __shared__ uint32_t Bs_hi[64][LDB];
    __shared__ uint32_t Bs_lo[64][LDB];

    int tid = threadIdx.x;
    int w = tid >> 5, lane = tid & 31;
    int wm = (w & 1) * 32;          // 2 warps down M
    int wn = (w >> 1) * 32;         // 2 warps across N
    int g = lane >> 2, tig = lane & 3;
    int blockRow = blockIdx.x * TM, blockCol = blockIdx.y * 64;

    // ldmatrix per-lane address components
    int a_r  = ((lane >> 3) & 1) * 8 + (lane & 7);
    int a_kc = (lane >> 4) * 4;
    int b_r  = lane & 7;
    int b_kc = ((lane >> 3) & 1) * 4;
    uint32_t sa_hi = (uint32_t)__cvta_generic_to_shared(As_hi);
    uint32_t sa_lo = (uint32_t)__cvta_generic_to_shared(As_lo);
    uint32_t sb_hi = (uint32_t)__cvta_generic_to_shared(Bs_hi);
    uint32_t sb_lo = (uint32_t)__cvta_generic_to_shared(Bs_lo);

    float acc[2][4][4];
#pragma unroll
    for (int mt = 0; mt < 2; mt++)
#pragma unroll
        for (int nt = 0; nt < 4; nt++)
#pragma unroll
            for (int q = 0; q < 4; q++) acc[mt][nt][q] = 0.0f;

    // staging: thread -> A row tid>>1 (0..63), kpair half (tid&1)*8 ; B same shape
    int arow = tid >> 1;
    int ahalf = (tid & 1) * 8;

    const uint32_t* pa_h = Ahi + (size_t)(blockRow + arow) * 128 + ahalf;
    const uint32_t* pa_l = Alo + (size_t)(blockRow + arow) * 128 + ahalf;
    const uint32_t* pb_h = Bhi + (size_t)(blockCol + arow) * 128 + ahalf;
    const uint32_t* pb_l = Blo + (size_t)(blockCol + arow) * 128 + ahalf;

    for (int k0 = 0; k0 < DD; k0 += KC) {
        int kp0 = k0 >> 1;
        uint4 ah0 = *(const uint4*)(pa_h + kp0);
        uint4 ah1 = *(const uint4*)(pa_h + kp0 + 4);
        uint4 al0 = *(const uint4*)(pa_l + kp0);
        uint4 al1 = *(const uint4*)(pa_l + kp0 + 4);
        uint4 bh0 = *(const uint4*)(pb_h + kp0);
        uint4 bh1 = *(const uint4*)(pb_h + kp0 + 4);
        uint4 bl0 = *(const uint4*)(pb_l + kp0);
        uint4 bl1 = *(const uint4*)(pb_l + kp0 + 4);
        *(uint4*)&As_hi[arow][ahalf] = ah0;
        *(uint4*)&As_hi[arow][ahalf + 4] = ah1;
        *(uint4*)&As_lo[arow][ahalf] = al0;
        *(uint4*)&As_lo[arow][ahalf + 4] = al1;
        *(uint4*)&Bs_hi[arow][ahalf] = bh0;
        *(uint4*)&Bs_hi[arow][ahalf + 4] = bh1;
        *(uint4*)&Bs_lo[arow][ahalf] = bl0;
        *(uint4*)&Bs_lo[arow][ahalf + 4] = bl1;
        __syncthreads();

#pragma unroll
        for (int kk = 0; kk < KC; kk += 16) {
            int kb = kk >> 1;
            uint32_t ah[2][4], al[2][4], bh[4][2], bl[4][2];
#pragma unroll
            for (int mt = 0; mt < 2; mt++) {
                uint32_t off = (uint32_t)((wm + mt * 16 + a_r) * LDA + kb + a_kc) * 4u;
                ldsm_x4(ah[mt], sa_hi + off);
                ldsm_x4(al[mt], sa_lo + off);
            }
#pragma unroll
            for (int nt = 0; nt < 4; nt++) {
                uint32_t off = (uint32_t)((wn + nt * 8 + b_r) * LDB + kb + b_kc) * 4u;
                ldsm_x2(bh[nt], sb_hi + off);
                ldsm_x2(bl[nt], sb_lo + off);
            }
#pragma unroll
            for (int mt = 0; mt < 2; mt++)
#pragma unroll
                for (int nt = 0; nt < 4; nt++) {
                    mma_bf16(acc[mt][nt], al[mt], bh[nt]);   // small terms first
                    mma_bf16(acc[mt][nt], ah[mt], bl[nt]);
                    mma_bf16(acc[mt][nt], ah[mt], bh[nt]);
                }
        }
        __syncthreads();
    }

    // ---- store C ----
#pragma unroll
    for (int mt = 0; mt < 2; mt++) {
        int r0 = blockRow + wm + mt * 16 + g;
        int r1 = r0 + 8;
#pragma unroll
        for (int nt = 0; nt < 4; nt++) {
            int col = blockCol + wn + nt * 8 + 2 * tig;
            if (r0 < M) *(float2*)(C + (size_t)r0 * DD + col) = make_float2(acc[mt][nt][0], acc[mt][nt][1]);
            if (r1 < M) *(float2*)(C + (size_t)r1 * DD + col) = make_float2(acc[mt][nt][2], acc[mt][nt][3]);
        }
    }

    // ---- fused attention dot products (layer 2 only) ----
    if (layer) {
#pragma unroll
        for (int mt = 0; mt < 2; mt++) {
            float s0 = 0.f, d0 = 0.f, s1 = 0.f, d1 = 0.f;
#pragma unroll
            for (int nt = 0; nt < 4; nt++) {
                int col = blockCol + wn + nt * 8 + 2 * tig;
                float a0 = asrc[col], a1 = asrc[col + 1];
                float t0 = adst[col], t1 = adst[col + 1];
                s0 += acc[mt][nt][0] * a0 + acc[mt][nt][1] * a1;
                d0 += acc[mt][nt][0] * t0 + acc[mt][nt][1] * t1;
                s1 += acc[mt][nt][2] * a0 + acc[mt][nt][3] * a1;
                d1 += acc[mt][nt][2] * t0 + acc[mt][nt][3] * t1;
            }
#pragma unroll
            for (int off = 1; off <= 2; off <<= 1) {
                s0 += __shfl_xor_sync(0xffffffffu, s0, off);
                d0 += __shfl_xor_sync(0xffffffffu, d0, off);
                s1 += __shfl_xor_sync(0xffffffffu, s1, off);
                d1 += __shfl_xor_sync(0xffffffffu, d1, off);
            }
            if (tig == 0) {
                int r0 = blockRow + wm + mt * 16 + g;
                int r1 = r0 + 8;
                if (r0 < M) { atomicAdd(&g_as[r0], s0); atomicAdd(&g_ad[r0], d0); }
                if (r1 < M) { atomicAdd(&g_as[r1], s1); atomicAdd(&g_ad[r1], d1); }
            }
        }
    }
}

// ---------------- GCN aggregation: warp per node, emits packed bf16 --------
__global__ void gcn_agg(const float* __restrict__ b1, int n) {
    int warp = (blockIdx.x * blockDim.x + threadIdx.x) >> 5;
    if (warp >= n) return;
    int lane = threadIdx.x & 31;
    float di = g_dinv[warp];
    int s = g_rowptr[warp], e = g_rowptr[warp + 1];
    float4 acc0 = make_float4(0.f, 0.f, 0.f, 0.f);
    float4 acc1 = make_float4(0.f, 0.f, 0.f, 0.f);
    int i = s;
    for (; i + 2 <= e; i += 2) {
        int s0 = g_srcs[i], s1 = g_srcs[i + 1];
        float w0 = di * g_dinv[s0];
        float w1 = di * g_dinv[s1];
        const float4* p0 = (const float4*)(g_xw1 + (size_t)s0 * DD);
        const float4* p1 = (const float4*)(g_xw1 + (size_t)s1 * DD);
        float4 a0 = p0[lane], a1 = p0[lane + 32];
        float4 c0 = p1[lane], c1 = p1[lane + 32];
        acc0.x += w0 * a0.x + w1 * c0.x; acc0.y += w0 * a0.y + w1 * c0.y;
        acc0.z += w0 * a0.z + w1 * c0.z; acc0.w += w0 * a0.w + w1 * c0.w;
        acc1.x += w0 * a1.x + w1 * c1.x; acc1.y += w0 * a1.y + w1 * c1.y;
        acc1.z += w0 * a1.z + w1 * c1.z; acc1.w += w0 * a1.w + w1 * c1.w;
    }
    if (i < e) {
        int s0 = g_srcs[i];
        float w0 = di * g_dinv[s0];
        const float4* p0 = (const float4*)(g_xw1 + (size_t)s0 * DD);
        float4 a0 = p0[lane], a1 = p0[lane + 32];
        acc0.x += w0 * a0.x; acc0.y += w0 * a0.y; acc0.z += w0 * a0.z; acc0.w += w0 * a0.w;
        acc1.x += w0 * a1.x; acc1.y += w0 * a1.y; acc1.z += w0 * a1.z; acc1.w += w0 * a1.w;
    }
    const float4* bb = (const float4*)b1;
    float4 b0 = bb[lane], b1v = bb[lane + 32];
    float o[8];
    o[0] = fmaxf(acc0.x + b0.x, 0.f);  o[1] = fmaxf(acc0.y + b0.y, 0.f);
    o[2] = fmaxf(acc0.z + b0.z, 0.f);  o[3] = fmaxf(acc0.w + b0.w, 0.f);
    o[4] = fmaxf(acc1.x + b1v.x, 0.f); o[5] = fmaxf(acc1.y + b1v.y, 0.f);
    o[6] = fmaxf(acc1.z + b1v.z, 0.f); o[7] = fmaxf(acc1.w + b1v.w, 0.f);
    uint2 h0, l0, h1, l1;
    split2(o[0], o[1], h0.x, l0.x); split2(o[2], o[3], h0.y, l0.y);
    split2(o[4], o[5], h1.x, l1.x); split2(o[6], o[7], h1.y, l1.y);
    size_t base = (size_t)warp * 128;
    *(uint2*)&g_x1hi[base + 2 * lane] = h0;
    *(uint2*)&g_x1lo[base + 2 * lane] = l0;
    *(uint2*)&g_x1hi[base + 64 + 2 * lane] = h1;
    *(uint2*)&g_x1lo[base + 64 + 2 * lane] = l1;
}

// ---------------- GAT aggregation: warp per node ---------------------------
__global__ void gat_agg(const float* __restrict__ b2, float* __restrict__ out, int n) {
    int warp = (blockIdx.x * blockDim.x + threadIdx.x) >> 5;
    if (warp >= n) return;
    int lane = threadIdx.x & 31;
    int s = g_rowptr[warp], e = g_rowptr[warp + 1];
    float ad_n = g_ad[warp];

    // pass 1: per-lane online softmax stats
    float m = -INFINITY, sum = 0.f;
    for (int i = s + lane; i < e; i += 32) {
        int src = g_srcs[i];
        float ev = g_as[src] + ad_n;
        ev = (ev >= 0.f) ? ev : 0.2f * ev;
        if (ev > m) {
            sum = sum * expf(m - ev) + 1.0f;
            m = ev;
        } else {
            sum += expf(ev - m);
        }
    }
#pragma unroll
    for (int off = 16; off > 0; off >>= 1) {
        float mo = __shfl_xor_sync(0xffffffffu, m, off);
        float so = __shfl_xor_sync(0xffffffffu, sum, off);
        float mn = fmaxf(m, mo);
        float sa = (m == mn) ? sum : sum * expf(m - mn);
        float sb = (mo == mn) ? so : so * expf(mo - mn);
        sum = sa + sb;
        m = mn;
    }
    float inv = 1.0f / (sum + 1e-16f);

    // pass 2: weighted accumulate, 2-edge unrolled
    float4 acc0 = make_float4(0.f, 0.f, 0.f, 0.f);
    float4 acc1 = make_float4(0.f, 0.f, 0.f, 0.f);
    int i = s;
    for (; i + 2 <= e; i += 2) {
        int s0 = g_srcs[i], s1 = g_srcs[i + 1];
        float e0 = g_as[s0] + ad_n;
        float e1 = g_as[s1] + ad_n;
        e0 = (e0 >= 0.f) ? e0 : 0.2f * e0;
        e1 = (e1 >= 0.f) ? e1 : 0.2f * e1;
        float w0 = expf(e0 - m) * inv;
        float w1 = expf(e1 - m) * inv;
        const float4* p0 = (const float4*)(g_xw2 + (size_t)s0 * DD);
        const float4* p1 = (const float4*)(g_xw2 + (size_t)s1 * DD);
        float4 a0 = p0[lane], a1 = p0[lane + 32];
        float4 c0 = p1[lane], c1 = p1[lane + 32];
        acc0.x += w0 * a0.x + w1 * c0.x; acc0.y += w0 * a0.y + w1 * c0.y;
        acc0.z += w0 * a0.z + w1 * c0.z; acc0.w += w0 * a0.w + w1 * c0.w;
        acc1.x += w0 * a1.x + w1 * c1.x; acc1.y += w0 * a1.y + w1 * c1.y;
        acc1.z += w0 * a1.z + w1 * c1.z; acc1.w += w0 * a1.w + w1 * c1.w;
    }
    if (i < e) {
        int s0 = g_srcs[i];
        float e0 = g_as[s0] + ad_n;
        e0 = (e0 >= 0.f) ? e0 : 0.2f * e0;
        float w0 = expf(e0 - m) * inv;
        const float4* p0 = (const float4*)(g_xw2 + (size_t)s0 * DD);
        float4 a0 = p0[lane], a1 = p0[lane + 32];
        acc0.x += w0 * a0.x; acc0.y += w0 * a0.y; acc0.z += w0 * a0.z; acc0.w += w0 * a0.w;
        acc1.x += w0 * a1.x; acc1.y += w0 * a1.y; acc1.z += w0 * a1.z; acc1.w += w0 * a1.w;
    }
    const float4* bb = (const float4*)b2;
    float4 b0 = bb[lane], b1v = bb[lane + 32];
    float4 o0 = make_float4(fmaxf(acc0.x + b0.x, 0.f), fmaxf(acc0.y + b0.y, 0.f),
                            fmaxf(acc0.z + b0.z, 0.f), fmaxf(acc0.w + b0.w, 0.f));
    float4 o1 = make_float4(fmaxf(acc1.x + b1v.x, 0.f), fmaxf(acc1.y + b1v.y, 0.f),
                            fmaxf(acc1.z + b1v.z, 0.f), fmaxf(acc1.w + b1v.w, 0.f));
    float4* op = (float4*)(out + (size_t)warp * DD);
    op[lane] = o0;
    op[lane + 32] = o1;
}

// ---------------- launch ----------------------------------------------------
static cudaStream_t s_side = nullptr;
static cudaEvent_t ev_fork = nullptr, ev_join = nullptr;

extern "C" void kernel_launch(void* const* d_in, const int* in_sizes, int n_in,
                              void* d_out, int out_size) {
    const float* x       = (const float*)d_in[0];
    const int*   ei      = (const int*)  d_in[1];
    const float* W1      = (const float*)d_in[2];
    const float* b1      = (const float*)d_in[3];
    const float* W2      = (const float*)d_in[4];
    const float* att_src = (const float*)d_in[5];
    const float* att_dst = (const float*)d_in[6];
    const float* b2      = (const float*)d_in[7];
    float* out = (float*)d_out;

    int n = in_sizes[0] / DD;
    int E = in_sizes[1] / 2;
    if (n > N_MAX) n = N_MAX;
    if (E > E_MAX) E = E_MAX;
    const int* src = ei;
    const int* dst = ei + E;
    int nb = (n + 255) / 256;

    if (!s_side) {   // first call is the (non-capture) correctness run
        cudaStreamCreateWithFlags(&s_side, cudaStreamNonBlocking);
        cudaEventCreateWithFlags(&ev_fork, cudaEventDisableTiming);
        cudaEventCreateWithFlags(&ev_join, cudaEventDisableTiming);
    }

    dim3 ggrid((n + TM - 1) / TM, 4);   // 64x64 tiles over [M,256]
    int splitThreads = 65536 + n * 64;

    // fork: CSR build on side stream; split + GEMM1 on main stream.
    // Enqueue order keeps sgemm_pk at capture-launch index 3 (ncu samples #3).
    cudaEventRecord(ev_fork, 0);
    cudaStreamWaitEvent(s_side, ev_fork, 0);

    k_count<<<(E + 255) / 256, 256, 0, s_side>>>(dst, E);          // 0
    k_scan1<<<nb, 256, 0, s_side>>>(n);                            // 1
    k_split<<<(splitThreads + 255) / 256, 256>>>(x, W1, W2, n);    // 2 (main)
    sgemm_pk<<<ggrid, 128>>>(n, nullptr, nullptr, 0);              // 3 (main, profiled)
    k_scan2<<<1, 32, 0, s_side>>>(nb, n);                          // 4
    k_scan3_self<<<(n + 255) / 256, 256, 0, s_side>>>(n);          // 5
    k_scatter<<<(E + 255) / 256, 256, 0, s_side>>>(src, dst, E);   // 6
    cudaEventRecord(ev_join, s_side);

    cudaStreamWaitEvent(0, ev_join, 0);                            // CSR ready

    gcn_agg<<<(n + 7) / 8, 256>>>(b1, n);                          // 7
    sgemm_pk<<<ggrid, 128>>>(n, att_src, att_dst, 1);              // 8
    gat_agg<<<(n + 7) / 8, 256>>>(b2, out, n);                     // 9
}

// round 12
// speedup vs baseline: 1.7782x; 1.0768x over previous
#include <cuda_runtime.h>
#include <cuda_bf16.h>
#include <math.h>
#include <stdint.h>

#define DD 256
#define N_MAX 10000
#define NPAD 10112            // 158 * 64, covers last GEMM tile rows
#define E_MAX 320000
#define ET_MAX (E_MAX + N_MAX)
#define NB_MAX 64

// ---------------- scratch (device globals; no allocation allowed) ----------
__device__ float g_xw1[N_MAX * DD];        // x @ W1 (fp32, read by gcn_agg)
__device__ float g_xw2[N_MAX * DD];        // x1 @ W2 (fp32, read by gat_agg)
__device__ uint32_t g_Ahi[NPAD * 128];     // x split, packed bf16x2 [row][kpair]
__device__ uint32_t g_Alo[NPAD * 128];
__device__ uint32_t g_x1hi[NPAD * 128];    // relu(GCN) split, packed
__device__ uint32_t g_x1lo[NPAD * 128];
__device__ uint32_t g_B1hi[256 * 128];     // W1 split, packed [col][kpair]
__device__ uint32_t g_B1lo[256 * 128];
__device__ uint32_t g_B2hi[256 * 128];     // W2 split
__device__ uint32_t g_B2lo[256 * 128];
__device__ float g_as[N_MAX];              // xw2 . att_src  (per node)
__device__ float g_ad[N_MAX];              // xw2 . att_dst
__device__ float g_dinv[N_MAX];
__device__ int   g_cnt[N_MAX];             // zero-init at load; re-zeroed each run
__device__ int   g_rowptr[N_MAX + 1];
__device__ int   g_wp[N_MAX];
__device__ int   g_srcs[ET_MAX];
__device__ int   g_bsum[NB_MAX];
__device__ int   g_boff[NB_MAX];

// split two fp32 into packed bf16x2 hi and lo (element0 in low half)
__device__ __forceinline__ void split2(float x0, float x1, uint32_t& hi, uint32_t& lo) {
    __nv_bfloat162 h = __floats2bfloat162_rn(x0, x1);
    float2 hf = __bfloat1622float2(h);
    __nv_bfloat162 l = __floats2bfloat162_rn(x0 - hf.x, x1 - hf.y);
    hi = *(uint32_t*)&h;
    lo = *(uint32_t*)&l;
}

// ---------------- CSR build -------------------------------------------------
__global__ void k_count(const int* __restrict__ dst, int E) {
    int e = blockIdx.x * blockDim.x + threadIdx.x;
    if (e < E) atomicAdd(&g_cnt[dst[e]], 1);
}

// scan1: deg = cnt + 1 (self loop), local prefix + block sums + dinv
__global__ void k_scan1(int n) {
    int i = blockIdx.x * 256 + threadIdx.x;
    int c = (i < n) ? g_cnt[i] + 1 : 0;
    if (i < n) g_dinv[i] = rsqrtf((float)c);
    int lane = threadIdx.x & 31, w = threadIdx.x >> 5;
    int v = c;
#pragma unroll
    for (int o = 1; o < 32; o <<= 1) {
        int t = __shfl_up_sync(0xffffffffu, v, o);
        if (lane >= o) v += t;
    }
    __shared__ int ws[8];
    if (lane == 31) ws[w] = v;
    __syncthreads();
    if (w == 0 && lane < 8) {
        int s = ws[lane];
#pragma unroll
        for (int o = 1; o < 8; o <<= 1) {
            int t = __shfl_up_sync(0xffu, s, o);
            if (lane >= o) s += t;
        }
        ws[lane] = s;
    }
    __syncthreads();
    int excl = v - c + (w ? ws[w - 1] : 0);
    if (i < n) g_rowptr[i] = excl;
    if (threadIdx.x == 0) g_bsum[blockIdx.x] = ws[7];
}

__global__ void k_scan2(int nb, int n) {
    int lane = threadIdx.x;
    int v0 = (lane < nb) ? g_bsum[lane] : 0;
    int v1 = (lane + 32 < nb) ? g_bsum[lane + 32] : 0;
    int s0 = v0, s1 = v1;
#pragma unroll
    for (int o = 1; o < 32; o <<= 1) {
        int t = __shfl_up_sync(0xffffffffu, s0, o);
        if (lane >= o) s0 += t;
        int t1 = __shfl_up_sync(0xffffffffu, s1, o);
        if (lane >= o) s1 += t1;
    }
    int tot0 = __shfl_sync(0xffffffffu, s0, 31);
    s1 += tot0;
    g_boff[lane] = s0 - v0;
    g_boff[lane + 32] = s1 - v1;
    if (lane == 31) g_rowptr[n] = s1;
}

// stage 3: apply offsets + self-loop + cursors + zero att dots + re-zero cnt
__global__ void k_scan3_self(int n) {
    int i = blockIdx.x * blockDim.x + threadIdx.x;
    if (i < n) {
        int p = g_rowptr[i] + g_boff[i >> 8];
        g_rowptr[i] = p;
        g_srcs[p] = i;
        g_wp[i] = p + 1;
        g_as[i] = 0.0f;      // fused-dot accumulators for layer 2
        g_ad[i] = 0.0f;
        g_cnt[i] = 0;        // ready for next run (after scan1 consumed it)
    }
}

__global__ void k_scatter(const int* __restrict__ src, const int* __restrict__ dst, int E) {
    int e = blockIdx.x * blockDim.x + threadIdx.x;
    if (e < E) {
        int d = dst[e];
        int pos = atomicAdd(&g_wp[d], 1);
        g_srcs[pos] = src[e];
    }
}

// ---------------- merged pre-split kernel -----------------------------------
__global__ void k_split(const float* __restrict__ x, const float* __restrict__ W1,
                        const float* __restrict__ W2, int n) {
    int t = blockIdx.x * blockDim.x + threadIdx.x;
    if (t < 65536) {
        int sel = t >> 15;
        int u = t & 32767;
        int kp = u >> 8, nn = u & 255;
        const float* W = sel ? W2 : W1;
        uint32_t* oh = sel ? g_B2hi : g_B1hi;
        uint32_t* ol = sel ? g_B2lo : g_B1lo;
        float w0 = W[(2 * kp) * 256 + nn];
        float w1 = W[(2 * kp + 1) * 256 + nn];
        uint32_t h, l;
        split2(w0, w1, h, l);
        oh[nn * 128 + kp] = h;
        ol[nn * 128 + kp] = l;
    } else {
        int i = t - 65536;
        if (i < n * 64) {
            float4 v = ((const float4*)x)[i];
            uint2 h, l;
            split2(v.x, v.y, h.x, l.x);
            split2(v.z, v.w, h.y, l.y);
            *(uint2*)&g_Ahi[(size_t)i * 2] = h;
            *(uint2*)&g_Alo[(size_t)i * 2] = l;
        }
    }
}

// ---------------- bf16x3 tensor GEMM, cp.async double-buffered --------------
// block tile 64x64, 4 warps (2m x 2n), warp tile 32x32, mma m16n8k16 bf16.
// 2-stage ping-pong smem pipeline: LDGSTS stage k+1 overlaps MMA on stage k.
// D += Al*Bh + Ah*Bl + Ah*Bh, fp32 accumulate.

__device__ __forceinline__ void mma_bf16(float* c, const uint32_t* a, const uint32_t* b) {
    asm volatile(
        "mma.sync.aligned.m16n8k16.row.col.f32.bf16.bf16.f32 "
        "{%0,%1,%2,%3},{%4,%5,%6,%7},{%8,%9},{%0,%1,%2,%3};"
        : "+f"(c[0]), "+f"(c[1]), "+f"(c[2]), "+f"(c[3])
        : "r"(a[0]), "r"(a[1]), "r"(a[2]), "r"(a[3]), "r"(b[0]), "r"(b[1]));
}

__device__ __forceinline__ void ldsm_x4(uint32_t* r, uint32_t saddr) {
    asm volatile("ldmatrix.sync.aligned.m8n8.x4.shared.b16 {%0,%1,%2,%3}, [%4];"
        : "=r"(r[0]), "=r"(r[1]), "=r"(r[2]), "=r"(r[3]) : "r"(saddr));
}
__device__ __forceinline__ void ldsm_x2(uint32_t* r, uint32_t saddr) {
    asm volatile("ldmatrix.sync.aligned.m8n8.x2.shared.b16 {%0,%1}, [%2];"
        : "=r"(r[0]), "=r"(r[1]) : "r"(saddr));
}
__device__ __forceinline__ void cp16(uint32_t saddr, const void* gaddr) {
    asm volatile("cp.async.cg.shared.global [%0], [%1], 16;"
        :: "r"(saddr), "l"(gaddr));
}

#define KC 32
#define LDA 20   // u32 stride; row pitch 80B -> ldmatrix conflict-free, 16B aligned
#define TM 64    // block tile rows
#define BUFSZ (TM * LDA * 4)   // 5120 bytes per array per stage
#define NSTAGE 8               // DD / KC

__global__ void __launch_bounds__(128, 5)
sgemm_pk(int M, const float* __restrict__ asrc, const float* __restrict__ adst, int layer) {
    const uint32_t* __restrict__ Ahi = layer ? g_x1hi : g_Ahi;
    const uint32_t* __restrict__ Alo = layer ? g_x1lo : g_Alo;
    const uint32_t* __restrict__ Bhi = layer ? g_B2hi : g_B1hi;
    const uint32_t* __restrict__ Blo = layer ? g_B2lo : g_B1lo;
    float* __restrict__ C = layer ? g_xw2 : g_xw1;

    __shared__ __align__(16) uint32_t As_hi[2][TM][LDA];
    __shared__ __align__(16) uint32_t As_lo[2][TM][LDA];
    __shared__ __align__(16) uint32_t Bs_hi[2][64][LDA];
    __shared__ __align__(16) uint32_t Bs_lo[2][64][LDA];

    int tid = threadIdx.x;
    int w = tid >> 5, lane = tid & 31;
    int wm = (w & 1) * 32;          // 2 warps down M
    int wn = (w >> 1) * 32;         // 2 warps across N
    int g = lane >> 2, tig = lane & 3;
    int blockRow = blockIdx.x * TM, blockCol = blockIdx.y * 64;

    // ldmatrix per-lane address components
    int a_r  = ((lane >> 3) & 1) * 8 + (lane & 7);
    int a_kc = (lane >> 4) * 4;
    int b_r  = lane & 7;
    int b_kc = ((lane >> 3) & 1) * 4;
    uint32_t sa_hi = (uint32_t)__cvta_generic_to_shared(As_hi);
    uint32_t sa_lo = (uint32_t)__cvta_generic_to_shared(As_lo);
    uint32_t sb_hi = (uint32_t)__cvta_generic_to_shared(Bs_hi);
    uint32_t sb_lo = (uint32_t)__cvta_generic_to_shared(Bs_lo);

    float acc[2][4][4];
#pragma unroll
    for (int mt = 0; mt < 2; mt++)
#pragma unroll
        for (int nt = 0; nt < 4; nt++)
#pragma unroll
            for (int q = 0; q < 4; q++) acc[mt][nt][q] = 0.0f;

    // staging: thread -> row tid>>1 (0..63), kpair half (tid&1)*8 (A and B alike)
    int arow = tid >> 1;
    int ahalf = (tid & 1) * 8;
    uint32_t stA = (uint32_t)(arow * LDA + ahalf) * 4u;   // byte offset within a stage

    const uint32_t* pa_h = Ahi + (size_t)(blockRow + arow) * 128 + ahalf;
    const uint32_t* pa_l = Alo + (size_t)(blockRow + arow) * 128 + ahalf;
    const uint32_t* pb_h = Bhi + (size_t)(blockCol + arow) * 128 + ahalf;
    const uint32_t* pb_l = Blo + (size_t)(blockCol + arow) * 128 + ahalf;

    auto issue = [&](int s, int buf) {
        int kp0 = s * (KC / 2);
        uint32_t o = stA + buf * BUFSZ;
        cp16(sa_hi + o,      pa_h + kp0);
        cp16(sa_hi + o + 16, pa_h + kp0 + 4);
        cp16(sa_lo + o,      pa_l + kp0);
        cp16(sa_lo + o + 16, pa_l + kp0 + 4);
        cp16(sb_hi + o,      pb_h + kp0);
        cp16(sb_hi + o + 16, pb_h + kp0 + 4);
        cp16(sb_lo + o,      pb_l + kp0);
        cp16(sb_lo + o + 16, pb_l + kp0 + 4);
    };

    // prologue: stage 0 in flight
    issue(0, 0);
    asm volatile("cp.async.commit_group;");

#pragma unroll
    for (int it = 0; it < NSTAGE; it++) {
        if (it + 1 < NSTAGE) {
            issue(it + 1, (it + 1) & 1);
            asm volatile("cp.async.commit_group;");
            asm volatile("cp.async.wait_group 1;");
        } else {
            asm volatile("cp.async.wait_group 0;");
        }
        __syncthreads();
        uint32_t bofs = (uint32_t)(it & 1) * BUFSZ;

#pragma unroll
        for (int kk = 0; kk < KC; kk += 16) {
            int kb = kk >> 1;
            uint32_t ah[2][4], al[2][4], bh[4][2], bl[4][2];
#pragma unroll
            for (int mt = 0; mt < 2; mt++) {
                uint32_t off = (uint32_t)((wm + mt * 16 + a_r) * LDA + kb + a_kc) * 4u + bofs;
                ldsm_x4(ah[mt], sa_hi + off);
                ldsm_x4(al[mt], sa_lo + off);
            }
#pragma unroll
            for (int nt = 0; nt < 4; nt++) {
                uint32_t off = (uint32_t)((wn + nt * 8 + b_r) * LDA + kb + b_kc) * 4u + bofs;
                ldsm_x2(bh[nt], sb_hi + off);
                ldsm_x2(bl[nt], sb_lo + off);
            }
#pragma unroll
            for (int mt = 0; mt < 2; mt++)
#pragma unroll
                for (int nt = 0; nt < 4; nt++) {
                    mma_bf16(acc[mt][nt], al[mt], bh[nt]);   // small terms first
                    mma_bf16(acc[mt][nt], ah[mt], bl[nt]);
                    mma_bf16(acc[mt][nt], ah[mt], bh[nt]);
                }
        }
        __syncthreads();
    }

    // ---- store C ----
#pragma unroll
    for (int mt = 0; mt < 2; mt++) {
        int r0 = blockRow + wm + mt * 16 + g;
        int r1 = r0 + 8;
#pragma unroll
        for (int nt = 0; nt < 4; nt++) {
            int col = blockCol + wn + nt * 8 + 2 * tig;
            if (r0 < M) *(float2*)(C + (size_t)r0 * DD + col) = make_float2(acc[mt][nt][0], acc[mt][nt][1]);
            if (r1 < M) *(float2*)(C + (size_t)r1 * DD + col) = make_float2(acc[mt][nt][2], acc[mt][nt][3]);
        }
    }

    // ---- fused attention dot products (layer 2 only) ----
    if (layer) {
#pragma unroll
        for (int mt = 0; mt < 2; mt++) {
            float s0 = 0.f, d0 = 0.f, s1 = 0.f, d1 = 0.f;
#pragma unroll
            for (int nt = 0; nt < 4; nt++) {
                int col = blockCol + wn + nt * 8 + 2 * tig;
                float a0 = asrc[col], a1 = asrc[col + 1];
                float t0 = adst[col], t1 = adst[col + 1];
                s0 += acc[mt][nt][0] * a0 + acc[mt][nt][1] * a1;
                d0 += acc[mt][nt][0] * t0 + acc[mt][nt][1] * t1;
                s1 += acc[mt][nt][2] * a0 + acc[mt][nt][3] * a1;
                d1 += acc[mt][nt][2] * t0 + acc[mt][nt][3] * t1;
            }
#pragma unroll
            for (int off = 1; off <= 2; off <<= 1) {
                s0 += __shfl_xor_sync(0xffffffffu, s0, off);
                d0 += __shfl_xor_sync(0xffffffffu, d0, off);
                s1 += __shfl_xor_sync(0xffffffffu, s1, off);
                d1 += __shfl_xor_sync(0xffffffffu, d1, off);
            }
            if (tig == 0) {
                int r0 = blockRow + wm + mt * 16 + g;
                int r1 = r0 + 8;
                if (r0 < M) { atomicAdd(&g_as[r0], s0); atomicAdd(&g_ad[r0], d0); }
                if (r1 < M) { atomicAdd(&g_as[r1], s1); atomicAdd(&g_ad[r1], d1); }
            }
        }
    }
}

// ---------------- GCN aggregation: warp per node, emits packed bf16 --------
__global__ void gcn_agg(const float* __restrict__ b1, int n) {
    int warp = (blockIdx.x * blockDim.x + threadIdx.x) >> 5;
    if (warp >= n) return;
    int lane = threadIdx.x & 31;
    float di = g_dinv[warp];
    int s = g_rowptr[warp], e = g_rowptr[warp + 1];
    float4 acc0 = make_float4(0.f, 0.f, 0.f, 0.f);
    float4 acc1 = make_float4(0.f, 0.f, 0.f, 0.f);
    int i = s;
    for (; i + 2 <= e; i += 2) {
        int s0 = g_srcs[i], s1 = g_srcs[i + 1];
        float w0 = di * g_dinv[s0];
        float w1 = di * g_dinv[s1];
        const float4* p0 = (const float4*)(g_xw1 + (size_t)s0 * DD);
        const float4* p1 = (const float4*)(g_xw1 + (size_t)s1 * DD);
        float4 a0 = p0[lane], a1 = p0[lane + 32];
        float4 c0 = p1[lane], c1 = p1[lane + 32];
        acc0.x += w0 * a0.x + w1 * c0.x; acc0.y += w0 * a0.y + w1 * c0.y;
        acc0.z += w0 * a0.z + w1 * c0.z; acc0.w += w0 * a0.w + w1 * c0.w;
        acc1.x += w0 * a1.x + w1 * c1.x; acc1.y += w0 * a1.y + w1 * c1.y;
        acc1.z += w0 * a1.z + w1 * c1.z; acc1.w += w0 * a1.w + w1 * c1.w;
    }
    if (i < e) {
        int s0 = g_srcs[i];
        float w0 = di * g_dinv[s0];
        const float4* p0 = (const float4*)(g_xw1 + (size_t)s0 * DD);
        float4 a0 = p0[lane], a1 = p0[lane + 32];
        acc0.x += w0 * a0.x; acc0.y += w0 * a0.y; acc0.z += w0 * a0.z; acc0.w += w0 * a0.w;
        acc1.x += w0 * a1.x; acc1.y += w0 * a1.y; acc1.z += w0 * a1.z; acc1.w += w0 * a1.w;
    }
    const float4* bb = (const float4*)b1;
    float4 b0 = bb[lane], b1v = bb[lane + 32];
    float o[8];
    o[0] = fmaxf(acc0.x + b0.x, 0.f);  o[1] = fmaxf(acc0.y + b0.y, 0.f);
    o[2] = fmaxf(acc0.z + b0.z, 0.f);  o[3] = fmaxf(acc0.w + b0.w, 0.f);
    o[4] = fmaxf(acc1.x + b1v.x, 0.f); o[5] = fmaxf(acc1.y + b1v.y, 0.f);
    o[6] = fmaxf(acc1.z + b1v.z, 0.f); o[7] = fmaxf(acc1.w + b1v.w, 0.f);
    uint2 h0, l0, h1, l1;
    split2(o[0], o[1], h0.x, l0.x); split2(o[2], o[3], h0.y, l0.y);
    split2(o[4], o[5], h1.x, l1.x); split2(o[6], o[7], h1.y, l1.y);
    size_t base = (size_t)warp * 128;
    *(uint2*)&g_x1hi[base + 2 * lane] = h0;
    *(uint2*)&g_x1lo[base + 2 * lane] = l0;
    *(uint2*)&g_x1hi[base + 64 + 2 * lane] = h1;
    *(uint2*)&g_x1lo[base + 64 + 2 * lane] = l1;
}

// ---------------- GAT aggregation: warp per node ---------------------------
__global__ void gat_agg(const float* __restrict__ b2, float* __restrict__ out, int n) {
    int warp = (blockIdx.x * blockDim.x + threadIdx.x) >> 5;
    if (warp >= n) return;
    int lane = threadIdx.x & 31;
    int s = g_rowptr[warp], e = g_rowptr[warp + 1];
    float ad_n = g_ad[warp];

    // pass 1: per-lane online softmax stats
    float m = -INFINITY, sum = 0.f;
    for (int i = s + lane; i < e; i += 32) {
        int src = g_srcs[i];
        float ev = g_as[src] + ad_n;
        ev = (ev >= 0.f) ? ev : 0.2f * ev;
        if (ev > m) {
            sum = sum * expf(m - ev) + 1.0f;
            m = ev;
        } else {
            sum += expf(ev - m);
        }
    }
#pragma unroll
    for (int off = 16; off > 0; off >>= 1) {
        float mo = __shfl_xor_sync(0xffffffffu, m, off);
        float so = __shfl_xor_sync(0xffffffffu, sum, off);
        float mn = fmaxf(m, mo);
        float sa = (m == mn) ? sum : sum * expf(m - mn);
        float sb = (mo == mn) ? so : so * expf(mo - mn);
        sum = sa + sb;
        m = mn;
    }
    float inv = 1.0f / (sum + 1e-16f);

    // pass 2: weighted accumulate, 2-edge unrolled
    float4 acc0 = make_float4(0.f, 0.f, 0.f, 0.f);
    float4 acc1 = make_float4(0.f, 0.f, 0.f, 0.f);
    int i = s;
    for (; i + 2 <= e; i += 2) {
        int s0 = g_srcs[i], s1 = g_srcs[i + 1];
        float e0 = g_as[s0] + ad_n;
        float e1 = g_as[s1] + ad_n;
        e0 = (e0 >= 0.f) ? e0 : 0.2f * e0;
        e1 = (e1 >= 0.f) ? e1 : 0.2f * e1;
        float w0 = expf(e0 - m) * inv;
        float w1 = expf(e1 - m) * inv;
        const float4* p0 = (const float4*)(g_xw2 + (size_t)s0 * DD);
        const float4* p1 = (const float4*)(g_xw2 + (size_t)s1 * DD);
        float4 a0 = p0[lane], a1 = p0[lane + 32];
        float4 c0 = p1[lane], c1 = p1[lane + 32];
        acc0.x += w0 * a0.x + w1 * c0.x; acc0.y += w0 * a0.y + w1 * c0.y;
        acc0.z += w0 * a0.z + w1 * c0.z; acc0.w += w0 * a0.w + w1 * c0.w;
        acc1.x += w0 * a1.x + w1 * c1.x; acc1.y += w0 * a1.y + w1 * c1.y;
        acc1.z += w0 * a1.z + w1 * c1.z; acc1.w += w0 * a1.w + w1 * c1.w;
    }
    if (i < e) {
        int s0 = g_srcs[i];
        float e0 = g_as[s0] + ad_n;
        e0 = (e0 >= 0.f) ? e0 : 0.2f * e0;
        float w0 = expf(e0 - m) * inv;
        const float4* p0 = (const float4*)(g_xw2 + (size_t)s0 * DD);
        float4 a0 = p0[lane], a1 = p0[lane + 32];
        acc0.x += w0 * a0.x; acc0.y += w0 * a0.y; acc0.z += w0 * a0.z; acc0.w += w0 * a0.w;
        acc1.x += w0 * a1.x; acc1.y += w0 * a1.y; acc1.z += w0 * a1.z; acc1.w += w0 * a1.w;
    }
    const float4* bb = (const float4*)b2;
    float4 b0 = bb[lane], b1v = bb[lane + 32];
    float4 o0 = make_float4(fmaxf(acc0.x + b0.x, 0.f), fmaxf(acc0.y + b0.y, 0.f),
                            fmaxf(acc0.z + b0.z, 0.f), fmaxf(acc0.w + b0.w, 0.f));
    float4 o1 = make_float4(fmaxf(acc1.x + b1v.x, 0.f), fmaxf(acc1.y + b1v.y, 0.f),
                            fmaxf(acc1.z + b1v.z, 0.f), fmaxf(acc1.w + b1v.w, 0.f));
    float4* op = (float4*)(out + (size_t)warp * DD);
    op[lane] = o0;
    op[lane + 32] = o1;
}

// ---------------- launch ----------------------------------------------------
static cudaStream_t s_side = nullptr;
static cudaEvent_t ev_fork = nullptr, ev_join = nullptr;

extern "C" void kernel_launch(void* const* d_in, const int* in_sizes, int n_in,
                              void* d_out, int out_size) {
    const float* x       = (const float*)d_in[0];
    const int*   ei      = (const int*)  d_in[1];
    const float* W1      = (const float*)d_in[2];
    const float* b1      = (const float*)d_in[3];
    const float* W2      = (const float*)d_in[4];
    const float* att_src = (const float*)d_in[5];
    const float* att_dst = (const float*)d_in[6];
    const float* b2      = (const float*)d_in[7];
    float* out = (float*)d_out;

    int n = in_sizes[0] / DD;
    int E = in_sizes[1] / 2;
    if (n > N_MAX) n = N_MAX;
    if (E > E_MAX) E = E_MAX;
    const int* src = ei;
    const int* dst = ei + E;
    int nb = (n + 255) / 256;

    if (!s_side) {   // first call is the (non-capture) correctness run
        cudaStreamCreateWithFlags(&s_side, cudaStreamNonBlocking);
        cudaEventCreateWithFlags(&ev_fork, cudaEventDisableTiming);
        cudaEventCreateWithFlags(&ev_join, cudaEventDisableTiming);
    }

    dim3 ggrid((n + TM - 1) / TM, 4);   // 64x64 tiles over [M,256]
    int splitThreads = 65536 + n * 64;

    // fork: CSR build on side stream; split + GEMM1 on main stream.
    // Enqueue order keeps sgemm_pk at capture-launch index 3 (ncu samples #3).
    cudaEventRecord(ev_fork, 0);
    cudaStreamWaitEvent(s_side, ev_fork, 0);

    k_count<<<(E + 255) / 256, 256, 0, s_side>>>(dst, E);          // 0
    k_scan1<<<nb, 256, 0, s_side>>>(n);                            // 1
    k_split<<<(splitThreads + 255) / 256, 256>>>(x, W1, W2, n);    // 2 (main)
    sgemm_pk<<<ggrid, 128>>>(n, nullptr, nullptr, 0);              // 3 (main, profiled)
    k_scan2<<<1, 32, 0, s_side>>>(nb, n);                          // 4
    k_scan3_self<<<(n + 255) / 256, 256, 0, s_side>>>(n);          // 5
    k_scatter<<<(E + 255) / 256, 256, 0, s_side>>>(src, dst, E);   // 6
    cudaEventRecord(ev_join, s_side);

    cudaStreamWaitEvent(0, ev_join, 0);                            // CSR ready

    gcn_agg<<<(n + 7) / 8, 256>>>(b1, n);                          // 7
    sgemm_pk<<<ggrid, 128>>>(n, att_src, att_dst, 1);              // 8
    gat_agg<<<(n + 7) / 8, 256>>>(b2, out, n);                     // 9
}